// round 10
// baseline (speedup 1.0000x reference)
#include <cuda_runtime.h>
#include <cuda_bf16.h>
#include <mma.h>
#include <type_traits>

// MonarchAttention on GB300 — WMMA bf16 3-term-split engine, v3:
// dual-tile CTAs (256 thr / 8 warps; warp w -> tile w>>2, m-tile w&3),
// col-major C (conflict-free softmax/writeout), halved barrier count/tile.
// B=4,H=16 -> BH=64; N=4096, D=64, b=m=64, STEPS=3.

using namespace nvcuda;
typedef unsigned int u32;

#define SCALE 0.125f
#define LDB 72       // bf16 tile row stride
#define LDC 68       // f32 C stride (col-major: C[n*LDC+m])

#define T_AH 0
#define T_AL 9216
#define T_BH 18432
#define T_BL 27648
#define T_C  36864
#define TILE 54272
#define OFF_ENT 108544     // f32[128] (2 tiles x 64)
#define OFF_W   109056     // f32[128]
#define SMEM_ALL 109568

__device__ float g_qmean[262144];     // [bh][s][d]
__device__ float g_ent  [262144];     // [bh][s][j]
__device__ float g_qbar [16777216];   // [bh][j][s][d]
__device__ float g_kbar [16777216];   // [bh][s][j][d]
__device__ float g_vbar [16777216];   // [bh][s][j][d]

// ---------------------------------------------------------------------------
__device__ __forceinline__ u32 pack2(float a, float b) {
    return (u32)__bfloat16_as_ushort(__float2bfloat16(a)) |
           ((u32)__bfloat16_as_ushort(__float2bfloat16(b)) << 16);
}
// 64x64 f32 (row stride rs) -> hi/lo bf16 tiles (row-major, LDB). 256 thr.
__device__ __forceinline__ void stageHL(__nv_bfloat16* Th, __nv_bfloat16* Tl,
                                        const float* src, int rs, int tid) {
#pragma unroll
    for (int it = 0; it < 4; ++it) {
        int lin = it * 256 + tid;            // 1024 float4 chunks
        int r = lin >> 4, c4 = (lin & 15) << 2;
        float4 v = *reinterpret_cast<const float4*>(src + r * rs + c4);
        float h0 = __bfloat162float(__float2bfloat16(v.x));
        float h1 = __bfloat162float(__float2bfloat16(v.y));
        float h2 = __bfloat162float(__float2bfloat16(v.z));
        float h3 = __bfloat162float(__float2bfloat16(v.w));
        uint2 H = make_uint2(pack2(v.x, v.y), pack2(v.z, v.w));
        uint2 L = make_uint2(pack2(v.x - h0, v.y - h1), pack2(v.z - h2, v.w - h3));
        *reinterpret_cast<uint2*>(Th + r * LDB + c4) = H;
        *reinterpret_cast<uint2*>(Tl + r * LDB + c4) = L;
    }
}
// one register row f[64] -> row r of hi/lo tiles
__device__ __forceinline__ void stageRow(__nv_bfloat16* Th, __nv_bfloat16* Tl,
                                         const float* f, int r) {
#pragma unroll
    for (int c = 0; c < 64; c += 4) {
        float h0 = __bfloat162float(__float2bfloat16(f[c]));
        float h1 = __bfloat162float(__float2bfloat16(f[c + 1]));
        float h2 = __bfloat162float(__float2bfloat16(f[c + 2]));
        float h3 = __bfloat162float(__float2bfloat16(f[c + 3]));
        *reinterpret_cast<uint2*>(Th + r * LDB + c) =
            make_uint2(pack2(f[c], f[c + 1]), pack2(f[c + 2], f[c + 3]));
        *reinterpret_cast<uint2*>(Tl + r * LDB + c) =
            make_uint2(pack2(f[c] - h0, f[c + 1] - h1),
                       pack2(f[c + 2] - h2, f[c + 3] - h3));
    }
}

// ---------------------------------------------------------------------------
// C(col-major, LDC) = A x B, 3-term bf16 split. One warp: rows [mt*16,+16),
// all 4 n-tiles.  AROW/BROW as before.
// ---------------------------------------------------------------------------
template <bool AROW, bool BROW>
__device__ __forceinline__ void wgemm3(const __nv_bfloat16* Ah, const __nv_bfloat16* Al,
                                       const __nv_bfloat16* Bh, const __nv_bfloat16* Bl,
                                       float* C, int mt) {
    using LA = typename std::conditional<AROW, wmma::row_major, wmma::col_major>::type;
    using LB = typename std::conditional<BROW, wmma::row_major, wmma::col_major>::type;
    wmma::fragment<wmma::matrix_a, 16, 16, 16, __nv_bfloat16, LA> ah[4], al[4];
    int m0 = mt << 4;
#pragma unroll
    for (int kt = 0; kt < 4; ++kt) {
        int aoff = AROW ? m0 * LDB + (kt << 4) : m0 + (kt << 4) * LDB;
        wmma::load_matrix_sync(ah[kt], Ah + aoff, LDB);
        wmma::load_matrix_sync(al[kt], Al + aoff, LDB);
    }
#pragma unroll
    for (int nt = 0; nt < 4; ++nt) {
        wmma::fragment<wmma::accumulator, 16, 16, 16, float> c;
        wmma::fill_fragment(c, 0.0f);
#pragma unroll
        for (int kt = 0; kt < 4; ++kt) {
            int boff = BROW ? (kt << 4) * LDB + (nt << 4) : (kt << 4) + (nt << 4) * LDB;
            wmma::fragment<wmma::matrix_b, 16, 16, 16, __nv_bfloat16, LB> bh, bl;
            wmma::load_matrix_sync(bh, Bh + boff, LDB);
            wmma::load_matrix_sync(bl, Bl + boff, LDB);
            wmma::mma_sync(c, ah[kt], bh, c);
            wmma::mma_sync(c, ah[kt], bl, c);
            wmma::mma_sync(c, al[kt], bh, c);
        }
        wmma::store_matrix_sync(C + m0 + (nt << 4) * LDC, c, LDC, wmma::mem_col_major);
    }
}

// ---------------------------------------------------------------------------
__global__ void qmean_kernel(const float* __restrict__ Q) {
    int bid = blockIdx.x;
    int bh = bid >> 4;
    int s = ((bid & 15) << 2) + (threadIdx.x >> 6);
    int d = threadIdx.x & 63;
    const float* base = Q + bh * 262144 + s * 64 + d;
    float acc = 0.f;
#pragma unroll 16
    for (int i = 0; i < 64; ++i) acc += base[i * 4096];
    g_qmean[(bh << 6 | s) * 64 + d] = acc * (1.0f / 64.0f);
}

// ---------------------------------------------------------------------------
// B: per (bh,j): S=scale*qbar_j K^T; R=softmax_t; ent; kbar=R K; (vbar=R V)
// grid 2048 (2 j per CTA), 256 thr
// ---------------------------------------------------------------------------
__global__ void __launch_bounds__(256)
bstep_kernel(const float* __restrict__ Kg, const float* __restrict__ Vg,
             int use_qmean, int do_vbar) {
    int bid = blockIdx.x, bh = bid >> 5, jp = (bid & 31) << 1;
    extern __shared__ char sm[];
    int tid = threadIdx.x, wid = tid >> 5;
    int wp = wid >> 2, mt = wid & 3;                  // warp's tile + m-tile
    char* tb[2] = {sm, sm + TILE};

    // stage: A_p = qbar/qmean, B_p = K
#pragma unroll
    for (int p = 0; p < 2; ++p) {
        const float* qb = use_qmean ? (g_qmean + (bh << 12))
                                    : (g_qbar + bh * 262144 + (jp + p) * 4096);
        stageHL((__nv_bfloat16*)(tb[p] + T_AH), (__nv_bfloat16*)(tb[p] + T_AL),
                qb, 64, tid);
        stageHL((__nv_bfloat16*)(tb[p] + T_BH), (__nv_bfloat16*)(tb[p] + T_BL),
                Kg + bh * 262144 + (jp + p) * 4096, 64, tid);
    }
    __syncthreads();

    // GEMM1: S[s][t] = qbar(s,d).K(t,d)  (B col_major view)
    wgemm3<true, false>((__nv_bfloat16*)(tb[wp] + T_AH), (__nv_bfloat16*)(tb[wp] + T_AL),
                        (__nv_bfloat16*)(tb[wp] + T_BH), (__nv_bfloat16*)(tb[wp] + T_BL),
                        (float*)(tb[wp] + T_C), mt);
    __syncthreads();

    // softmax over t: 128 threads (tile p = tid>>6, row s = tid&63)
    if (tid < 128) {
        int p = tid >> 6, s = tid & 63, j = jp + p;
        float* C = (float*)(tb[p] + T_C);
        float f[64], mx = -1e30f;
#pragma unroll
        for (int c = 0; c < 64; ++c) {
            f[c] = C[c * LDC + s] * SCALE;
            mx = fmaxf(mx, f[c]);
        }
        float sum = 0.f;
#pragma unroll
        for (int c = 0; c < 64; ++c) { f[c] = __expf(f[c] - mx); sum += f[c]; }
        float inv = 1.0f / sum, lsum = __logf(sum), e = 0.f;
#pragma unroll
        for (int c = 0; c < 64; ++c) {
            float rv = f[c] * inv;
            e += rv * (__logf(fmaxf(f[c], 1e-37f)) - lsum);
            f[c] = rv;
        }
        g_ent[((bh << 6) + s) * 64 + j] = -e;
        stageRow((__nv_bfloat16*)(tb[p] + T_AH), (__nv_bfloat16*)(tb[p] + T_AL), f, s);
    }
    __syncthreads();

    // GEMM2: kbar = R(s,t) K(t,d), both row-major
    wgemm3<true, true>((__nv_bfloat16*)(tb[wp] + T_AH), (__nv_bfloat16*)(tb[wp] + T_AL),
                       (__nv_bfloat16*)(tb[wp] + T_BH), (__nv_bfloat16*)(tb[wp] + T_BL),
                       (float*)(tb[wp] + T_C), mt);
    __syncthreads();

    if (tid < 128) {   // writeout kbar
        int p = tid >> 6, s = tid & 63, j = jp + p;
        const float* C = (float*)(tb[p] + T_C);
        float* o = g_kbar + bh * 262144 + s * 4096 + (j << 6);
#pragma unroll
        for (int c = 0; c < 64; c += 4)
            *reinterpret_cast<float4*>(o + c) =
                make_float4(C[c * LDC + s], C[(c + 1) * LDC + s],
                            C[(c + 2) * LDC + s], C[(c + 3) * LDC + s]);
    }
    if (do_vbar) {
        // stage V over K (K dead); C reads above are per-thread ordered
#pragma unroll
        for (int p = 0; p < 2; ++p)
            stageHL((__nv_bfloat16*)(tb[p] + T_BH), (__nv_bfloat16*)(tb[p] + T_BL),
                    Vg + bh * 262144 + (jp + p) * 4096, 64, tid);
        __syncthreads();
        wgemm3<true, true>((__nv_bfloat16*)(tb[wp] + T_AH), (__nv_bfloat16*)(tb[wp] + T_AL),
                           (__nv_bfloat16*)(tb[wp] + T_BH), (__nv_bfloat16*)(tb[wp] + T_BL),
                           (float*)(tb[wp] + T_C), mt);
        __syncthreads();
        if (tid < 128) {
            int p = tid >> 6, s = tid & 63, j = jp + p;
            const float* C = (float*)(tb[p] + T_C);
            float* o = g_vbar + bh * 262144 + s * 4096 + (j << 6);
#pragma unroll
            for (int c = 0; c < 64; c += 4)
                *reinterpret_cast<float4*>(o + c) =
                    make_float4(C[c * LDC + s], C[(c + 1) * LDC + s],
                                C[(c + 2) * LDC + s], C[(c + 3) * LDC + s]);
        }
    }
}

// ---------------------------------------------------------------------------
// C (fused): per (bh,s): SL = scale*Q kbar^T + ent; L = softmax_j
//   non-final: qbar[j][d] = (sum_i L[i][j] Q[i][d]) / (sum_i L[i][j])
//   final:     out[i][d] = sum_j L[i][j] vbar[j][d]
// grid 2048 (2 s per CTA), 256 thr
// ---------------------------------------------------------------------------
__global__ void __launch_bounds__(256)
cstep_kernel(const float* __restrict__ Qg, float* __restrict__ out, int is_final) {
    int bid = blockIdx.x, bh = bid >> 5, sp = (bid & 31) << 1;
    extern __shared__ char sm[];
    int tid = threadIdx.x, wid = tid >> 5;
    int wp = wid >> 2, mt = wid & 3;
    char* tb[2] = {sm, sm + TILE};
    float* sEnt = (float*)(sm + OFF_ENT);   // [2][64]
    float* sW = (float*)(sm + OFF_W);       // [2][64]

#pragma unroll
    for (int p = 0; p < 2; ++p) {
        stageHL((__nv_bfloat16*)(tb[p] + T_AH), (__nv_bfloat16*)(tb[p] + T_AL),
                Qg + bh * 262144 + (sp + p) * 64, 4096, tid);       // Q rows i
        stageHL((__nv_bfloat16*)(tb[p] + T_BH), (__nv_bfloat16*)(tb[p] + T_BL),
                g_kbar + bh * 262144 + (sp + p) * 4096, 64, tid);   // kbar rows j
    }
    if (tid < 128)
        sEnt[tid] = g_ent[((bh << 6) + sp + (tid >> 6)) * 64 + (tid & 63)];
    __syncthreads();

    // GEMM1: SL[i][j] = Q(i,d).kbar(j,d)
    wgemm3<true, false>((__nv_bfloat16*)(tb[wp] + T_AH), (__nv_bfloat16*)(tb[wp] + T_AL),
                        (__nv_bfloat16*)(tb[wp] + T_BH), (__nv_bfloat16*)(tb[wp] + T_BL),
                        (float*)(tb[wp] + T_C), mt);
    __syncthreads();

    if (tid < 128) {
        int p = tid >> 6, i = tid & 63;
        float* C = (float*)(tb[p] + T_C);
        const float* ent = sEnt + (p << 6);
        float f[64], mx = -1e30f;
#pragma unroll
        for (int c = 0; c < 64; ++c) {
            f[c] = C[c * LDC + i] * SCALE + ent[c];
            mx = fmaxf(mx, f[c]);
        }
        float sum = 0.f;
#pragma unroll
        for (int c = 0; c < 64; ++c) { f[c] = __expf(f[c] - mx); sum += f[c]; }
        float inv = 1.0f / sum;
#pragma unroll
        for (int c = 0; c < 64; ++c) f[c] *= inv;   // L row i
        stageRow((__nv_bfloat16*)(tb[p] + T_BH), (__nv_bfloat16*)(tb[p] + T_BL), f, i);
        if (!is_final) {
#pragma unroll
            for (int c = 0; c < 64; ++c) C[c * LDC + i] = f[c];   // L fp32 for w
        }
    }
    if (is_final) {   // stage vbar over Q (Q dead in final GEMM)
#pragma unroll
        for (int p = 0; p < 2; ++p)
            stageHL((__nv_bfloat16*)(tb[p] + T_AH), (__nv_bfloat16*)(tb[p] + T_AL),
                    g_vbar + bh * 262144 + (sp + p) * 4096, 64, tid);
    }
    __syncthreads();

    if (!is_final) {
        if (tid < 128) {   // w_j = sum_i L[i][j], rotated conflict-free
            int p = tid >> 6, j = tid & 63;
            const float* C = (float*)(tb[p] + T_C);
            float w = 0.f;
#pragma unroll 8
            for (int i = 0; i < 64; ++i) w += C[j * LDC + ((i + j) & 63)];
            sW[(p << 6) + j] = 1.0f / w;
        }
        __syncthreads();
        // qbar_num(j,d) = sum_i L(i,j) Q(i,d): A = L col_major view, B = Q row_major
        wgemm3<false, true>((__nv_bfloat16*)(tb[wp] + T_BH), (__nv_bfloat16*)(tb[wp] + T_BL),
                            (__nv_bfloat16*)(tb[wp] + T_AH), (__nv_bfloat16*)(tb[wp] + T_AL),
                            (float*)(tb[wp] + T_C), mt);
        __syncthreads();
        if (tid < 128) {
            int p = tid >> 6, j = tid & 63;
            const float* C = (float*)(tb[p] + T_C);
            float iw = sW[(p << 6) + j];
            float* o = g_qbar + bh * 262144 + j * 4096 + (sp + p) * 64;
#pragma unroll
            for (int c = 0; c < 64; c += 4)
                *reinterpret_cast<float4*>(o + c) =
                    make_float4(C[c * LDC + j] * iw, C[(c + 1) * LDC + j] * iw,
                                C[(c + 2) * LDC + j] * iw, C[(c + 3) * LDC + j] * iw);
        }
    } else {
        // out(i,d) = sum_j L(i,j) vbar(j,d): both row_major
        wgemm3<true, true>((__nv_bfloat16*)(tb[wp] + T_BH), (__nv_bfloat16*)(tb[wp] + T_BL),
                           (__nv_bfloat16*)(tb[wp] + T_AH), (__nv_bfloat16*)(tb[wp] + T_AL),
                           (float*)(tb[wp] + T_C), mt);
        __syncthreads();
        if (tid < 128) {
            int p = tid >> 6, i = tid & 63;
            const float* C = (float*)(tb[p] + T_C);
            float* o = out + bh * 262144 + i * 4096 + (sp + p) * 64;
#pragma unroll
            for (int c = 0; c < 64; c += 4)
                *reinterpret_cast<float4*>(o + c) =
                    make_float4(C[c * LDC + i], C[(c + 1) * LDC + i],
                                C[(c + 2) * LDC + i], C[(c + 3) * LDC + i]);
        }
    }
}

// ---------------------------------------------------------------------------
extern "C" void kernel_launch(void* const* d_in, const int* in_sizes, int n_in,
                              void* d_out, int out_size) {
    const float* Q = (const float*)d_in[0];
    const float* K = (const float*)d_in[1];
    const float* V = (const float*)d_in[2];
    float* out = (float*)d_out;

    cudaFuncSetAttribute(bstep_kernel, cudaFuncAttributeMaxDynamicSharedMemorySize, SMEM_ALL);
    cudaFuncSetAttribute(cstep_kernel, cudaFuncAttributeMaxDynamicSharedMemorySize, SMEM_ALL);

    // step 0 (uniform L -> qbar == per-s mean of Q)
    qmean_kernel<<<1024, 256>>>(Q);
    bstep_kernel<<<2048, 256, SMEM_ALL>>>(K, V, 1, 0);
    cstep_kernel<<<2048, 256, SMEM_ALL>>>(Q, out, 0);
    // step 1
    bstep_kernel<<<2048, 256, SMEM_ALL>>>(K, V, 0, 0);
    cstep_kernel<<<2048, 256, SMEM_ALL>>>(Q, out, 0);
    // step 2
    bstep_kernel<<<2048, 256, SMEM_ALL>>>(K, V, 0, 1);   // + vbar
    cstep_kernel<<<2048, 256, SMEM_ALL>>>(Q, out, 1);    // final: out = L vbar
}

// round 11
// speedup vs baseline: 1.2201x; 1.2201x over previous
#include <cuda_runtime.h>
#include <cuda_bf16.h>
#include <mma.h>
#include <type_traits>

// MonarchAttention on GB300 — WMMA bf16 3-term-split engine, v4:
// v1 skeleton (128 thr, warp=m-tile) + col-major C (conflict-free softmax)
// + intermediates stored as pre-split bf16 hi/lo planes (cp.async staging).
// B=4,H=16 -> BH=64; N=4096, D=64, b=m=64, STEPS=3.

using namespace nvcuda;
typedef unsigned int u32;

#define SCALE 0.125f
#define LDB 72   // bf16 tile row stride (144B)
#define LDC 68   // f32 C stride, COL-major: C[n*LDC+m]

#define OFF_AH 0
#define OFF_AL 9216
#define OFF_BH 18432
#define OFF_BL 27648
#define OFF_C  36864
#define OFF_W  54272          // 128 f32 (ent + w)
#define OFF_VH 54784
#define OFF_VL 64000
#define SMEM_SMALL 54784
#define SMEM_BIG   73216

__device__ float g_ent[262144];                 // [bh][s][j]
__device__ __nv_bfloat16 g_qmeanH[262144], g_qmeanL[262144];
__device__ __nv_bfloat16 g_qbarH[16777216], g_qbarL[16777216];  // [bh][j][s][d]
__device__ __nv_bfloat16 g_kbarH[16777216], g_kbarL[16777216];  // [bh][s][j][d]
__device__ __nv_bfloat16 g_vbarH[16777216], g_vbarL[16777216];  // [bh][s][j][d]

// ---------------------------------------------------------------------------
__device__ __forceinline__ u32 smem_u32(const void* p) {
    u32 a;
    asm("{ .reg .u64 t; cvta.to.shared.u64 t, %1; cvt.u32.u64 %0, t; }"
        : "=r"(a) : "l"(p));
    return a;
}
__device__ __forceinline__ void cpa16(u32 s, const void* g) {
    asm volatile("cp.async.cg.shared.global [%0], [%1], 16;" :: "r"(s), "l"(g));
}
__device__ __forceinline__ void cpa_wait() {
    asm volatile("cp.async.wait_all;" ::: "memory");
}
__device__ __forceinline__ u32 pack2(float a, float b) {
    return (u32)__bfloat16_as_ushort(__float2bfloat16(a)) |
           ((u32)__bfloat16_as_ushort(__float2bfloat16(b)) << 16);
}
__device__ __forceinline__ void split8(const float* v, uint4& H, uint4& L) {
    float h[8];
#pragma unroll
    for (int i = 0; i < 8; ++i) h[i] = __bfloat162float(__float2bfloat16(v[i]));
    H = make_uint4(pack2(v[0], v[1]), pack2(v[2], v[3]),
                   pack2(v[4], v[5]), pack2(v[6], v[7]));
    L = make_uint4(pack2(v[0] - h[0], v[1] - h[1]), pack2(v[2] - h[2], v[3] - h[3]),
                   pack2(v[4] - h[4], v[5] - h[5]), pack2(v[6] - h[6], v[7] - h[7]));
}

// fp32 64x64 (row stride rs) -> split hi/lo tiles (row-major LDB). 128 thr.
__device__ __forceinline__ void stageHL(__nv_bfloat16* Th, __nv_bfloat16* Tl,
                                        const float* src, int rs, int tid) {
#pragma unroll
    for (int it = 0; it < 8; ++it) {
        int lin = it * 128 + tid;            // 1024 float4 chunks
        int r = lin >> 4, c4 = (lin & 15) << 2;
        float4 v = *reinterpret_cast<const float4*>(src + r * rs + c4);
        float h0 = __bfloat162float(__float2bfloat16(v.x));
        float h1 = __bfloat162float(__float2bfloat16(v.y));
        float h2 = __bfloat162float(__float2bfloat16(v.z));
        float h3 = __bfloat162float(__float2bfloat16(v.w));
        *reinterpret_cast<uint2*>(Th + r * LDB + c4) =
            make_uint2(pack2(v.x, v.y), pack2(v.z, v.w));
        *reinterpret_cast<uint2*>(Tl + r * LDB + c4) =
            make_uint2(pack2(v.x - h0, v.y - h1), pack2(v.z - h2, v.w - h3));
    }
}
// pre-split plane (64x64 bf16, contiguous) -> tile via cp.async. 128 thr.
__device__ __forceinline__ void copyTile(u32 sbase, const __nv_bfloat16* g, int tid) {
#pragma unroll
    for (int it = 0; it < 4; ++it) {
        int idx = it * 128 + tid;            // 512 chunks of 16B
        int row = idx >> 3, ch = idx & 7;
        cpa16(sbase + row * 144 + ch * 16, g + row * 64 + ch * 8);
    }
}
// one register row f[64] -> row r of hi/lo tiles
__device__ __forceinline__ void stageRow(__nv_bfloat16* Th, __nv_bfloat16* Tl,
                                         const float* f, int r) {
#pragma unroll
    for (int c = 0; c < 64; c += 8) {
        uint4 H, L;
        split8(f + c, H, L);
        *reinterpret_cast<uint4*>(Th + r * LDB + c) = H;
        *reinterpret_cast<uint4*>(Tl + r * LDB + c) = L;
    }
}
// register row f[64] -> global hi/lo planes at base (row already applied)
__device__ __forceinline__ void storeRowHL(__nv_bfloat16* gH, __nv_bfloat16* gL,
                                           const float* f) {
#pragma unroll
    for (int c = 0; c < 64; c += 8) {
        uint4 H, L;
        split8(f + c, H, L);
        *reinterpret_cast<uint4*>(gH + c) = H;
        *reinterpret_cast<uint4*>(gL + c) = L;
    }
}

// ---------------------------------------------------------------------------
// C(COL-major) = A x B, 3-term bf16 split. Warp mt: rows [mt*16,16), 4 n-tiles.
// ---------------------------------------------------------------------------
template <bool AROW, bool BROW>
__device__ __forceinline__ void wgemm3(const __nv_bfloat16* Ah, const __nv_bfloat16* Al,
                                       const __nv_bfloat16* Bh, const __nv_bfloat16* Bl,
                                       float* C, int mt) {
    using LA = typename std::conditional<AROW, wmma::row_major, wmma::col_major>::type;
    using LB = typename std::conditional<BROW, wmma::row_major, wmma::col_major>::type;
    wmma::fragment<wmma::matrix_a, 16, 16, 16, __nv_bfloat16, LA> ah[4], al[4];
    int m0 = mt << 4;
#pragma unroll
    for (int kt = 0; kt < 4; ++kt) {
        int aoff = AROW ? m0 * LDB + (kt << 4) : m0 + (kt << 4) * LDB;
        wmma::load_matrix_sync(ah[kt], Ah + aoff, LDB);
        wmma::load_matrix_sync(al[kt], Al + aoff, LDB);
    }
#pragma unroll
    for (int nt = 0; nt < 4; ++nt) {
        wmma::fragment<wmma::accumulator, 16, 16, 16, float> c;
        wmma::fill_fragment(c, 0.0f);
#pragma unroll
        for (int kt = 0; kt < 4; ++kt) {
            int boff = BROW ? (kt << 4) * LDB + (nt << 4) : (kt << 4) + (nt << 4) * LDB;
            wmma::fragment<wmma::matrix_b, 16, 16, 16, __nv_bfloat16, LB> bh, bl;
            wmma::load_matrix_sync(bh, Bh + boff, LDB);
            wmma::load_matrix_sync(bl, Bl + boff, LDB);
            wmma::mma_sync(c, ah[kt], bh, c);
            wmma::mma_sync(c, ah[kt], bl, c);
            wmma::mma_sync(c, al[kt], bh, c);
        }
        wmma::store_matrix_sync(C + m0 + (nt << 4) * LDC, c, LDC, wmma::mem_col_major);
    }
}

// ---------------------------------------------------------------------------
// qmean (split bf16 output): qmean[bh][s][d] = mean_i Q[bh][i][s][d]
// ---------------------------------------------------------------------------
__global__ void qmean_kernel(const float* __restrict__ Q) {
    int bid = blockIdx.x;
    int bh = bid >> 4;
    int s = ((bid & 15) << 2) + (threadIdx.x >> 6);
    int d = threadIdx.x & 63;
    const float* base = Q + bh * 262144 + s * 64 + d;
    float acc = 0.f;
#pragma unroll 16
    for (int i = 0; i < 64; ++i) acc += base[i * 4096];
    acc *= (1.0f / 64.0f);
    float h = __bfloat162float(__float2bfloat16(acc));
    int o = (bh << 6 | s) * 64 + d;
    g_qmeanH[o] = __float2bfloat16(acc);
    g_qmeanL[o] = __float2bfloat16(acc - h);
}

// ---------------------------------------------------------------------------
// B: per (bh,j): S=scale*qbar_j K^T; R=softmax_t; ent; kbar=R K; (vbar=R V)
// grid 4096, 128 thr
// ---------------------------------------------------------------------------
__global__ void __launch_bounds__(128)
bstep_kernel(const float* __restrict__ Kg, const float* __restrict__ Vg,
             int use_qmean, int do_vbar) {
    int bid = blockIdx.x, bh = bid >> 6, j = bid & 63;
    extern __shared__ char sm[];
    __nv_bfloat16* Ah = (__nv_bfloat16*)(sm + OFF_AH);   // qbar -> R
    __nv_bfloat16* Al = (__nv_bfloat16*)(sm + OFF_AL);
    __nv_bfloat16* Kh = (__nv_bfloat16*)(sm + OFF_BH);
    __nv_bfloat16* Kl = (__nv_bfloat16*)(sm + OFF_BL);
    __nv_bfloat16* Vh = (__nv_bfloat16*)(sm + OFF_VH);
    __nv_bfloat16* Vl = (__nv_bfloat16*)(sm + OFF_VL);
    float* C = (float*)(sm + OFF_C);
    int tid = threadIdx.x, wid = tid >> 5;

    // A tiles: cp.async copies of pre-split planes (no ALU)
    int qoff = use_qmean ? (bh << 12) : (bh * 262144 + j * 4096);
    copyTile(smem_u32(Ah), (use_qmean ? g_qmeanH : g_qbarH) + qoff, tid);
    copyTile(smem_u32(Al), (use_qmean ? g_qmeanL : g_qbarL) + qoff, tid);
    // B tile: split K on stage
    stageHL(Kh, Kl, Kg + bh * 262144 + j * 4096, 64, tid);
    if (do_vbar) stageHL(Vh, Vl, Vg + bh * 262144 + j * 4096, 64, tid);
    cpa_wait();
    __syncthreads();

    // GEMM1: S[s][t] = qbar(s,d).K(t,d)  (B col_major view); C col-major
    wgemm3<true, false>(Ah, Al, Kh, Kl, C, wid);
    __syncthreads();

    if (tid < 64) {
        int s = tid;
        float f[64], mx = -1e30f;
#pragma unroll
        for (int c = 0; c < 64; ++c) {
            f[c] = C[c * LDC + s] * SCALE;     // conflict-free
            mx = fmaxf(mx, f[c]);
        }
        float sum = 0.f;
#pragma unroll
        for (int c = 0; c < 64; ++c) { f[c] = __expf(f[c] - mx); sum += f[c]; }
        float inv = 1.0f / sum, lsum = __logf(sum), e = 0.f;
#pragma unroll
        for (int c = 0; c < 64; ++c) {
            float rv = f[c] * inv;
            e += rv * (__logf(fmaxf(f[c], 1e-37f)) - lsum);
            f[c] = rv;
        }
        g_ent[((bh << 6) + s) * 64 + j] = -e;
        stageRow(Ah, Al, f, s);                // R replaces qbar
    }
    __syncthreads();

    // GEMM2: kbar = R(s,t) K(t,d)
    wgemm3<true, true>(Ah, Al, Kh, Kl, C, wid);
    __syncthreads();
    if (tid < 64) {
        int s = tid;
        float f[64];
#pragma unroll
        for (int c = 0; c < 64; ++c) f[c] = C[c * LDC + s];
        int o = bh * 262144 + s * 4096 + (j << 6);
        storeRowHL(g_kbarH + o, g_kbarL + o, f);
    }
    if (do_vbar) {
        __syncthreads();
        wgemm3<true, true>(Ah, Al, Vh, Vl, C, wid);
        __syncthreads();
        if (tid < 64) {
            int s = tid;
            float f[64];
#pragma unroll
            for (int c = 0; c < 64; ++c) f[c] = C[c * LDC + s];
            int o = bh * 262144 + s * 4096 + (j << 6);
            storeRowHL(g_vbarH + o, g_vbarL + o, f);
        }
    }
}

// ---------------------------------------------------------------------------
// C (fused): per (bh,s): SL = scale*Q kbar^T + ent; L = softmax_j
//   non-final: qbar[j][d] = (sum_i L[i][j] Q[i][d]) / (sum_i L[i][j])
//   final:     out[i][d] = sum_j L[i][j] vbar[j][d]
// grid 4096, 128 thr
// ---------------------------------------------------------------------------
__global__ void __launch_bounds__(128)
cstep_kernel(const float* __restrict__ Qg, float* __restrict__ out, int is_final) {
    int bid = blockIdx.x, bh = bid >> 6, s = bid & 63;
    extern __shared__ char sm[];
    __nv_bfloat16* Qh = (__nv_bfloat16*)(sm + OFF_AH);
    __nv_bfloat16* Ql = (__nv_bfloat16*)(sm + OFF_AL);
    __nv_bfloat16* Bh = (__nv_bfloat16*)(sm + OFF_BH);  // kbar -> L
    __nv_bfloat16* Bl = (__nv_bfloat16*)(sm + OFF_BL);
    __nv_bfloat16* Vh = (__nv_bfloat16*)(sm + OFF_VH);
    __nv_bfloat16* Vl = (__nv_bfloat16*)(sm + OFF_VL);
    float* C = (float*)(sm + OFF_C);
    float* sEnt = (float*)(sm + OFF_W);
    float* sW = sEnt + 64;
    int tid = threadIdx.x, wid = tid >> 5;

    // B tiles: pre-split kbar planes via cp.async; vbar too if final
    int koff = bh * 262144 + s * 4096;
    copyTile(smem_u32(Bh), g_kbarH + koff, tid);
    copyTile(smem_u32(Bl), g_kbarL + koff, tid);
    if (is_final) {
        copyTile(smem_u32(Vh), g_vbarH + koff, tid);
        copyTile(smem_u32(Vl), g_vbarL + koff, tid);
    }
    // A tile: split Q on stage (rows i, stride 4096)
    stageHL(Qh, Ql, Qg + bh * 262144 + s * 64, 4096, tid);
    if (tid < 64) sEnt[tid] = g_ent[((bh << 6) + s) * 64 + tid];
    cpa_wait();
    __syncthreads();

    // GEMM1: SL[i][j] = Q(i,d).kbar(j,d)
    wgemm3<true, false>(Qh, Ql, Bh, Bl, C, wid);
    __syncthreads();

    if (tid < 64) {
        int i = tid;
        float f[64], mx = -1e30f;
#pragma unroll
        for (int c = 0; c < 64; ++c) {
            f[c] = C[c * LDC + i] * SCALE + sEnt[c];
            mx = fmaxf(mx, f[c]);
        }
        float sum = 0.f;
#pragma unroll
        for (int c = 0; c < 64; ++c) { f[c] = __expf(f[c] - mx); sum += f[c]; }
        float inv = 1.0f / sum;
#pragma unroll
        for (int c = 0; c < 64; ++c) f[c] *= inv;     // L row i
        stageRow(Bh, Bl, f, i);                        // L replaces kbar
        if (!is_final) {
#pragma unroll
            for (int c = 0; c < 64; ++c) C[c * LDC + i] = f[c];  // L fp32 (conflict-free)
        }
    }
    __syncthreads();

    if (!is_final) {
        if (tid < 64) {    // w_j = sum_i L[i][j], rotated conflict-free
            int jj = tid;
            float w = 0.f;
#pragma unroll 8
            for (int i = 0; i < 64; ++i) w += C[jj * LDC + ((i + jj) & 63)];
            sW[jj] = 1.0f / w;
        }
        __syncthreads();
        // qbar_num(j,d) = sum_i L(i,j) Q(i,d): A = L col view, B = Q row
        wgemm3<false, true>(Bh, Bl, Qh, Ql, C, wid);
        __syncthreads();
        if (tid < 64) {
            int jj = tid;
            float iw = sW[jj];
            float f[64];
#pragma unroll
            for (int c = 0; c < 64; ++c) f[c] = C[c * LDC + jj] * iw;
            int o = bh * 262144 + jj * 4096 + (s << 6);
            storeRowHL(g_qbarH + o, g_qbarL + o, f);
        }
    } else {
        // out(i,d) = sum_j L(i,j) vbar(j,d)
        wgemm3<true, true>(Bh, Bl, Vh, Vl, C, wid);
        __syncthreads();
        if (tid < 64) {
            int i = tid;
            float* o = out + bh * 262144 + i * 4096 + (s << 6);
#pragma unroll
            for (int c = 0; c < 64; c += 4)
                *reinterpret_cast<float4*>(o + c) =
                    make_float4(C[c * LDC + i], C[(c + 1) * LDC + i],
                                C[(c + 2) * LDC + i], C[(c + 3) * LDC + i]);
        }
    }
}

// ---------------------------------------------------------------------------
extern "C" void kernel_launch(void* const* d_in, const int* in_sizes, int n_in,
                              void* d_out, int out_size) {
    const float* Q = (const float*)d_in[0];
    const float* K = (const float*)d_in[1];
    const float* V = (const float*)d_in[2];
    float* out = (float*)d_out;

    cudaFuncSetAttribute(bstep_kernel, cudaFuncAttributeMaxDynamicSharedMemorySize, SMEM_BIG);
    cudaFuncSetAttribute(cstep_kernel, cudaFuncAttributeMaxDynamicSharedMemorySize, SMEM_BIG);

    // step 0 (uniform L -> qbar == per-s mean of Q)
    qmean_kernel<<<1024, 256>>>(Q);
    bstep_kernel<<<4096, 128, SMEM_SMALL>>>(K, V, 1, 0);
    cstep_kernel<<<4096, 128, SMEM_SMALL>>>(Q, out, 0);
    // step 1
    bstep_kernel<<<4096, 128, SMEM_SMALL>>>(K, V, 0, 0);
    cstep_kernel<<<4096, 128, SMEM_SMALL>>>(Q, out, 0);
    // step 2
    bstep_kernel<<<4096, 128, SMEM_BIG>>>(K, V, 0, 1);   // + vbar
    cstep_kernel<<<4096, 128, SMEM_BIG>>>(Q, out, 1);    // final: out = L vbar
}

// round 12
// speedup vs baseline: 1.2311x; 1.0090x over previous
#include <cuda_runtime.h>
#include <cuda_bf16.h>
#include <mma.h>
#include <type_traits>

// MonarchAttention on GB300 — WMMA bf16 3-term-split engine, v5:
// v4 + interleaved accumulator chains in wgemm3 (acc[4] live across kt,
// A-fragments loaded once per kt) -> ~4x shorter GEMM critical path.
// B=4,H=16 -> BH=64; N=4096, D=64, b=m=64, STEPS=3.

using namespace nvcuda;
typedef unsigned int u32;

#define SCALE 0.125f
#define LDB 72   // bf16 tile row stride (144B)
#define LDC 68   // f32 C stride, COL-major: C[n*LDC+m]

#define OFF_AH 0
#define OFF_AL 9216
#define OFF_BH 18432
#define OFF_BL 27648
#define OFF_C  36864
#define OFF_W  54272          // 128 f32 (ent + w)
#define OFF_VH 54784
#define OFF_VL 64000
#define SMEM_SMALL 54784
#define SMEM_BIG   73216

__device__ float g_ent[262144];                 // [bh][s][j]
__device__ __nv_bfloat16 g_qmeanH[262144], g_qmeanL[262144];
__device__ __nv_bfloat16 g_qbarH[16777216], g_qbarL[16777216];  // [bh][j][s][d]
__device__ __nv_bfloat16 g_kbarH[16777216], g_kbarL[16777216];  // [bh][s][j][d]
__device__ __nv_bfloat16 g_vbarH[16777216], g_vbarL[16777216];  // [bh][s][j][d]

// ---------------------------------------------------------------------------
__device__ __forceinline__ u32 smem_u32(const void* p) {
    u32 a;
    asm("{ .reg .u64 t; cvta.to.shared.u64 t, %1; cvt.u32.u64 %0, t; }"
        : "=r"(a) : "l"(p));
    return a;
}
__device__ __forceinline__ void cpa16(u32 s, const void* g) {
    asm volatile("cp.async.cg.shared.global [%0], [%1], 16;" :: "r"(s), "l"(g));
}
__device__ __forceinline__ void cpa_wait() {
    asm volatile("cp.async.wait_all;" ::: "memory");
}
__device__ __forceinline__ u32 pack2(float a, float b) {
    return (u32)__bfloat16_as_ushort(__float2bfloat16(a)) |
           ((u32)__bfloat16_as_ushort(__float2bfloat16(b)) << 16);
}
__device__ __forceinline__ void split8(const float* v, uint4& H, uint4& L) {
    float h[8];
#pragma unroll
    for (int i = 0; i < 8; ++i) h[i] = __bfloat162float(__float2bfloat16(v[i]));
    H = make_uint4(pack2(v[0], v[1]), pack2(v[2], v[3]),
                   pack2(v[4], v[5]), pack2(v[6], v[7]));
    L = make_uint4(pack2(v[0] - h[0], v[1] - h[1]), pack2(v[2] - h[2], v[3] - h[3]),
                   pack2(v[4] - h[4], v[5] - h[5]), pack2(v[6] - h[6], v[7] - h[7]));
}

// fp32 64x64 (row stride rs) -> split hi/lo tiles (row-major LDB). 128 thr.
__device__ __forceinline__ void stageHL(__nv_bfloat16* Th, __nv_bfloat16* Tl,
                                        const float* src, int rs, int tid) {
#pragma unroll
    for (int it = 0; it < 8; ++it) {
        int lin = it * 128 + tid;            // 1024 float4 chunks
        int r = lin >> 4, c4 = (lin & 15) << 2;
        float4 v = *reinterpret_cast<const float4*>(src + r * rs + c4);
        float h0 = __bfloat162float(__float2bfloat16(v.x));
        float h1 = __bfloat162float(__float2bfloat16(v.y));
        float h2 = __bfloat162float(__float2bfloat16(v.z));
        float h3 = __bfloat162float(__float2bfloat16(v.w));
        *reinterpret_cast<uint2*>(Th + r * LDB + c4) =
            make_uint2(pack2(v.x, v.y), pack2(v.z, v.w));
        *reinterpret_cast<uint2*>(Tl + r * LDB + c4) =
            make_uint2(pack2(v.x - h0, v.y - h1), pack2(v.z - h2, v.w - h3));
    }
}
// pre-split plane (64x64 bf16, contiguous) -> tile via cp.async. 128 thr.
__device__ __forceinline__ void copyTile(u32 sbase, const __nv_bfloat16* g, int tid) {
#pragma unroll
    for (int it = 0; it < 4; ++it) {
        int idx = it * 128 + tid;            // 512 chunks of 16B
        int row = idx >> 3, ch = idx & 7;
        cpa16(sbase + row * 144 + ch * 16, g + row * 64 + ch * 8);
    }
}
// one register row f[64] -> row r of hi/lo tiles
__device__ __forceinline__ void stageRow(__nv_bfloat16* Th, __nv_bfloat16* Tl,
                                         const float* f, int r) {
#pragma unroll
    for (int c = 0; c < 64; c += 8) {
        uint4 H, L;
        split8(f + c, H, L);
        *reinterpret_cast<uint4*>(Th + r * LDB + c) = H;
        *reinterpret_cast<uint4*>(Tl + r * LDB + c) = L;
    }
}
// register row f[64] -> global hi/lo planes at base (row already applied)
__device__ __forceinline__ void storeRowHL(__nv_bfloat16* gH, __nv_bfloat16* gL,
                                           const float* f) {
#pragma unroll
    for (int c = 0; c < 64; c += 8) {
        uint4 H, L;
        split8(f + c, H, L);
        *reinterpret_cast<uint4*>(gH + c) = H;
        *reinterpret_cast<uint4*>(gL + c) = L;
    }
}

// ---------------------------------------------------------------------------
// C(COL-major) = A x B, 3-term bf16 split. Warp mt: rows [mt*16,16), 4 n-tiles.
// acc[4] live across the kt loop -> 4 interleavable mma chains.
// ---------------------------------------------------------------------------
template <bool AROW, bool BROW>
__device__ __forceinline__ void wgemm3(const __nv_bfloat16* Ah, const __nv_bfloat16* Al,
                                       const __nv_bfloat16* Bh, const __nv_bfloat16* Bl,
                                       float* C, int mt) {
    using LA = typename std::conditional<AROW, wmma::row_major, wmma::col_major>::type;
    using LB = typename std::conditional<BROW, wmma::row_major, wmma::col_major>::type;
    wmma::fragment<wmma::accumulator, 16, 16, 16, float> c[4];
#pragma unroll
    for (int nt = 0; nt < 4; ++nt) wmma::fill_fragment(c[nt], 0.0f);
    int m0 = mt << 4;
#pragma unroll
    for (int kt = 0; kt < 4; ++kt) {
        int aoff = AROW ? m0 * LDB + (kt << 4) : m0 + (kt << 4) * LDB;
        wmma::fragment<wmma::matrix_a, 16, 16, 16, __nv_bfloat16, LA> ah, al;
        wmma::load_matrix_sync(ah, Ah + aoff, LDB);
        wmma::load_matrix_sync(al, Al + aoff, LDB);
#pragma unroll
        for (int nt = 0; nt < 4; ++nt) {
            int boff = BROW ? (kt << 4) * LDB + (nt << 4) : (kt << 4) + (nt << 4) * LDB;
            wmma::fragment<wmma::matrix_b, 16, 16, 16, __nv_bfloat16, LB> bh, bl;
            wmma::load_matrix_sync(bh, Bh + boff, LDB);
            wmma::load_matrix_sync(bl, Bl + boff, LDB);
            wmma::mma_sync(c[nt], ah, bh, c[nt]);
            wmma::mma_sync(c[nt], ah, bl, c[nt]);
            wmma::mma_sync(c[nt], al, bh, c[nt]);
        }
    }
#pragma unroll
    for (int nt = 0; nt < 4; ++nt)
        wmma::store_matrix_sync(C + m0 + (nt << 4) * LDC, c[nt], LDC,
                                wmma::mem_col_major);
}

// ---------------------------------------------------------------------------
// qmean (split bf16 output): qmean[bh][s][d] = mean_i Q[bh][i][s][d]
// ---------------------------------------------------------------------------
__global__ void qmean_kernel(const float* __restrict__ Q) {
    int bid = blockIdx.x;
    int bh = bid >> 4;
    int s = ((bid & 15) << 2) + (threadIdx.x >> 6);
    int d = threadIdx.x & 63;
    const float* base = Q + bh * 262144 + s * 64 + d;
    float acc = 0.f;
#pragma unroll 16
    for (int i = 0; i < 64; ++i) acc += base[i * 4096];
    acc *= (1.0f / 64.0f);
    float h = __bfloat162float(__float2bfloat16(acc));
    int o = (bh << 6 | s) * 64 + d;
    g_qmeanH[o] = __float2bfloat16(acc);
    g_qmeanL[o] = __float2bfloat16(acc - h);
}

// ---------------------------------------------------------------------------
// B: per (bh,j): S=scale*qbar_j K^T; R=softmax_t; ent; kbar=R K; (vbar=R V)
// grid 4096, 128 thr
// ---------------------------------------------------------------------------
__global__ void __launch_bounds__(128)
bstep_kernel(const float* __restrict__ Kg, const float* __restrict__ Vg,
             int use_qmean, int do_vbar) {
    int bid = blockIdx.x, bh = bid >> 6, j = bid & 63;
    extern __shared__ char sm[];
    __nv_bfloat16* Ah = (__nv_bfloat16*)(sm + OFF_AH);   // qbar -> R
    __nv_bfloat16* Al = (__nv_bfloat16*)(sm + OFF_AL);
    __nv_bfloat16* Kh = (__nv_bfloat16*)(sm + OFF_BH);
    __nv_bfloat16* Kl = (__nv_bfloat16*)(sm + OFF_BL);
    __nv_bfloat16* Vh = (__nv_bfloat16*)(sm + OFF_VH);
    __nv_bfloat16* Vl = (__nv_bfloat16*)(sm + OFF_VL);
    float* C = (float*)(sm + OFF_C);
    int tid = threadIdx.x, wid = tid >> 5;

    // A tiles: cp.async copies of pre-split planes (no ALU)
    int qoff = use_qmean ? (bh << 12) : (bh * 262144 + j * 4096);
    copyTile(smem_u32(Ah), (use_qmean ? g_qmeanH : g_qbarH) + qoff, tid);
    copyTile(smem_u32(Al), (use_qmean ? g_qmeanL : g_qbarL) + qoff, tid);
    // B tile: split K on stage
    stageHL(Kh, Kl, Kg + bh * 262144 + j * 4096, 64, tid);
    if (do_vbar) stageHL(Vh, Vl, Vg + bh * 262144 + j * 4096, 64, tid);
    cpa_wait();
    __syncthreads();

    // GEMM1: S[s][t] = qbar(s,d).K(t,d)  (B col_major view); C col-major
    wgemm3<true, false>(Ah, Al, Kh, Kl, C, wid);
    __syncthreads();

    if (tid < 64) {
        int s = tid;
        float f[64], mx = -1e30f;
#pragma unroll
        for (int c = 0; c < 64; ++c) {
            f[c] = C[c * LDC + s] * SCALE;     // conflict-free
            mx = fmaxf(mx, f[c]);
        }
        float sum = 0.f;
#pragma unroll
        for (int c = 0; c < 64; ++c) { f[c] = __expf(f[c] - mx); sum += f[c]; }
        float inv = 1.0f / sum, lsum = __logf(sum), e = 0.f;
#pragma unroll
        for (int c = 0; c < 64; ++c) {
            float rv = f[c] * inv;
            e += rv * (__logf(fmaxf(f[c], 1e-37f)) - lsum);
            f[c] = rv;
        }
        g_ent[((bh << 6) + s) * 64 + j] = -e;
        stageRow(Ah, Al, f, s);                // R replaces qbar
    }
    __syncthreads();

    // GEMM2: kbar = R(s,t) K(t,d)
    wgemm3<true, true>(Ah, Al, Kh, Kl, C, wid);
    __syncthreads();
    if (tid < 64) {
        int s = tid;
        float f[64];
#pragma unroll
        for (int c = 0; c < 64; ++c) f[c] = C[c * LDC + s];
        int o = bh * 262144 + s * 4096 + (j << 6);
        storeRowHL(g_kbarH + o, g_kbarL + o, f);
    }
    if (do_vbar) {
        __syncthreads();
        wgemm3<true, true>(Ah, Al, Vh, Vl, C, wid);
        __syncthreads();
        if (tid < 64) {
            int s = tid;
            float f[64];
#pragma unroll
            for (int c = 0; c < 64; ++c) f[c] = C[c * LDC + s];
            int o = bh * 262144 + s * 4096 + (j << 6);
            storeRowHL(g_vbarH + o, g_vbarL + o, f);
        }
    }
}

// ---------------------------------------------------------------------------
// C (fused): per (bh,s): SL = scale*Q kbar^T + ent; L = softmax_j
//   non-final: qbar[j][d] = (sum_i L[i][j] Q[i][d]) / (sum_i L[i][j])
//   final:     out[i][d] = sum_j L[i][j] vbar[j][d]
// grid 4096, 128 thr
// ---------------------------------------------------------------------------
__global__ void __launch_bounds__(128)
cstep_kernel(const float* __restrict__ Qg, float* __restrict__ out, int is_final) {
    int bid = blockIdx.x, bh = bid >> 6, s = bid & 63;
    extern __shared__ char sm[];
    __nv_bfloat16* Qh = (__nv_bfloat16*)(sm + OFF_AH);
    __nv_bfloat16* Ql = (__nv_bfloat16*)(sm + OFF_AL);
    __nv_bfloat16* Bh = (__nv_bfloat16*)(sm + OFF_BH);  // kbar -> L
    __nv_bfloat16* Bl = (__nv_bfloat16*)(sm + OFF_BL);
    __nv_bfloat16* Vh = (__nv_bfloat16*)(sm + OFF_VH);
    __nv_bfloat16* Vl = (__nv_bfloat16*)(sm + OFF_VL);
    float* C = (float*)(sm + OFF_C);
    float* sEnt = (float*)(sm + OFF_W);
    float* sW = sEnt + 64;
    int tid = threadIdx.x, wid = tid >> 5;

    // B tiles: pre-split kbar planes via cp.async; vbar too if final
    int koff = bh * 262144 + s * 4096;
    copyTile(smem_u32(Bh), g_kbarH + koff, tid);
    copyTile(smem_u32(Bl), g_kbarL + koff, tid);
    if (is_final) {
        copyTile(smem_u32(Vh), g_vbarH + koff, tid);
        copyTile(smem_u32(Vl), g_vbarL + koff, tid);
    }
    // A tile: split Q on stage (rows i, stride 4096)
    stageHL(Qh, Ql, Qg + bh * 262144 + s * 64, 4096, tid);
    if (tid < 64) sEnt[tid] = g_ent[((bh << 6) + s) * 64 + tid];
    cpa_wait();
    __syncthreads();

    // GEMM1: SL[i][j] = Q(i,d).kbar(j,d)
    wgemm3<true, false>(Qh, Ql, Bh, Bl, C, wid);
    __syncthreads();

    if (tid < 64) {
        int i = tid;
        float f[64], mx = -1e30f;
#pragma unroll
        for (int c = 0; c < 64; ++c) {
            f[c] = C[c * LDC + i] * SCALE + sEnt[c];
            mx = fmaxf(mx, f[c]);
        }
        float sum = 0.f;
#pragma unroll
        for (int c = 0; c < 64; ++c) { f[c] = __expf(f[c] - mx); sum += f[c]; }
        float inv = 1.0f / sum;
#pragma unroll
        for (int c = 0; c < 64; ++c) f[c] *= inv;     // L row i
        stageRow(Bh, Bl, f, i);                        // L replaces kbar
        if (!is_final) {
#pragma unroll
            for (int c = 0; c < 64; ++c) C[c * LDC + i] = f[c];  // L fp32 (conflict-free)
        }
    }
    __syncthreads();

    if (!is_final) {
        if (tid < 64) {    // w_j = sum_i L[i][j], rotated conflict-free
            int jj = tid;
            float w = 0.f;
#pragma unroll 8
            for (int i = 0; i < 64; ++i) w += C[jj * LDC + ((i + jj) & 63)];
            sW[jj] = 1.0f / w;
        }
        __syncthreads();
        // qbar_num(j,d) = sum_i L(i,j) Q(i,d): A = L col view, B = Q row
        wgemm3<false, true>(Bh, Bl, Qh, Ql, C, wid);
        __syncthreads();
        if (tid < 64) {
            int jj = tid;
            float iw = sW[jj];
            float f[64];
#pragma unroll
            for (int c = 0; c < 64; ++c) f[c] = C[c * LDC + jj] * iw;
            int o = bh * 262144 + jj * 4096 + (s << 6);
            storeRowHL(g_qbarH + o, g_qbarL + o, f);
        }
    } else {
        // out(i,d) = sum_j L(i,j) vbar(j,d)
        wgemm3<true, true>(Bh, Bl, Vh, Vl, C, wid);
        __syncthreads();
        if (tid < 64) {
            int i = tid;
            float* o = out + bh * 262144 + i * 4096 + (s << 6);
#pragma unroll
            for (int c = 0; c < 64; c += 4)
                *reinterpret_cast<float4*>(o + c) =
                    make_float4(C[c * LDC + i], C[(c + 1) * LDC + i],
                                C[(c + 2) * LDC + i], C[(c + 3) * LDC + i]);
        }
    }
}

// ---------------------------------------------------------------------------
extern "C" void kernel_launch(void* const* d_in, const int* in_sizes, int n_in,
                              void* d_out, int out_size) {
    const float* Q = (const float*)d_in[0];
    const float* K = (const float*)d_in[1];
    const float* V = (const float*)d_in[2];
    float* out = (float*)d_out;

    cudaFuncSetAttribute(bstep_kernel, cudaFuncAttributeMaxDynamicSharedMemorySize, SMEM_BIG);
    cudaFuncSetAttribute(cstep_kernel, cudaFuncAttributeMaxDynamicSharedMemorySize, SMEM_BIG);

    // step 0 (uniform L -> qbar == per-s mean of Q)
    qmean_kernel<<<1024, 256>>>(Q);
    bstep_kernel<<<4096, 128, SMEM_SMALL>>>(K, V, 1, 0);
    cstep_kernel<<<4096, 128, SMEM_SMALL>>>(Q, out, 0);
    // step 1
    bstep_kernel<<<4096, 128, SMEM_SMALL>>>(K, V, 0, 0);
    cstep_kernel<<<4096, 128, SMEM_SMALL>>>(Q, out, 0);
    // step 2
    bstep_kernel<<<4096, 128, SMEM_BIG>>>(K, V, 0, 1);   // + vbar
    cstep_kernel<<<4096, 128, SMEM_BIG>>>(Q, out, 1);    // final: out = L vbar
}

// round 13
// speedup vs baseline: 1.2951x; 1.0520x over previous
#include <cuda_runtime.h>
#include <cuda_bf16.h>
#include <mma.h>
#include <type_traits>

// MonarchAttention on GB300 — WMMA bf16 3-term-split engine, v6:
// v5 + 128-thread softmax/writeout (2 thr/row, shfl-pair), log-free entropy,
// cp.async group overlap for final vbar tiles.
// B=4,H=16 -> BH=64; N=4096, D=64, b=m=64, STEPS=3.

using namespace nvcuda;
typedef unsigned int u32;

#define SCALE 0.125f
#define LDB 72   // bf16 tile row stride (144B)
#define LDC 68   // f32 C stride, COL-major: C[n*LDC+m]

#define OFF_AH 0
#define OFF_AL 9216
#define OFF_BH 18432
#define OFF_BL 27648
#define OFF_C  36864
#define OFF_W  54272          // 128 f32 (ent + w)
#define OFF_VH 54784
#define OFF_VL 64000
#define SMEM_SMALL 54784
#define SMEM_BIG   73216

__device__ float g_ent[262144];                 // [bh][s][j]
__device__ __nv_bfloat16 g_qmeanH[262144], g_qmeanL[262144];
__device__ __nv_bfloat16 g_qbarH[16777216], g_qbarL[16777216];  // [bh][j][s][d]
__device__ __nv_bfloat16 g_kbarH[16777216], g_kbarL[16777216];  // [bh][s][j][d]
__device__ __nv_bfloat16 g_vbarH[16777216], g_vbarL[16777216];  // [bh][s][j][d]

// ---------------------------------------------------------------------------
__device__ __forceinline__ u32 smem_u32(const void* p) {
    u32 a;
    asm("{ .reg .u64 t; cvta.to.shared.u64 t, %1; cvt.u32.u64 %0, t; }"
        : "=r"(a) : "l"(p));
    return a;
}
__device__ __forceinline__ void cpa16(u32 s, const void* g) {
    asm volatile("cp.async.cg.shared.global [%0], [%1], 16;" :: "r"(s), "l"(g));
}
__device__ __forceinline__ void cpa_commit() {
    asm volatile("cp.async.commit_group;" ::: "memory");
}
template <int N>
__device__ __forceinline__ void cpa_waitg() {
    asm volatile("cp.async.wait_group %0;" :: "n"(N) : "memory");
}
__device__ __forceinline__ u32 pack2(float a, float b) {
    return (u32)__bfloat16_as_ushort(__float2bfloat16(a)) |
           ((u32)__bfloat16_as_ushort(__float2bfloat16(b)) << 16);
}
__device__ __forceinline__ void split8(const float* v, uint4& H, uint4& L) {
    float h[8];
#pragma unroll
    for (int i = 0; i < 8; ++i) h[i] = __bfloat162float(__float2bfloat16(v[i]));
    H = make_uint4(pack2(v[0], v[1]), pack2(v[2], v[3]),
                   pack2(v[4], v[5]), pack2(v[6], v[7]));
    L = make_uint4(pack2(v[0] - h[0], v[1] - h[1]), pack2(v[2] - h[2], v[3] - h[3]),
                   pack2(v[4] - h[4], v[5] - h[5]), pack2(v[6] - h[6], v[7] - h[7]));
}

// fp32 64x64 (row stride rs) -> split hi/lo tiles (row-major LDB). 128 thr.
__device__ __forceinline__ void stageHL(__nv_bfloat16* Th, __nv_bfloat16* Tl,
                                        const float* src, int rs, int tid) {
#pragma unroll
    for (int it = 0; it < 8; ++it) {
        int lin = it * 128 + tid;            // 1024 float4 chunks
        int r = lin >> 4, c4 = (lin & 15) << 2;
        float4 v = *reinterpret_cast<const float4*>(src + r * rs + c4);
        float h0 = __bfloat162float(__float2bfloat16(v.x));
        float h1 = __bfloat162float(__float2bfloat16(v.y));
        float h2 = __bfloat162float(__float2bfloat16(v.z));
        float h3 = __bfloat162float(__float2bfloat16(v.w));
        *reinterpret_cast<uint2*>(Th + r * LDB + c4) =
            make_uint2(pack2(v.x, v.y), pack2(v.z, v.w));
        *reinterpret_cast<uint2*>(Tl + r * LDB + c4) =
            make_uint2(pack2(v.x - h0, v.y - h1), pack2(v.z - h2, v.w - h3));
    }
}
// pre-split plane (64x64 bf16, contiguous) -> tile via cp.async. 128 thr.
__device__ __forceinline__ void copyTile(u32 sbase, const __nv_bfloat16* g, int tid) {
#pragma unroll
    for (int it = 0; it < 4; ++it) {
        int idx = it * 128 + tid;            // 512 chunks of 16B
        int row = idx >> 3, ch = idx & 7;
        cpa16(sbase + row * 144 + ch * 16, g + row * 64 + ch * 8);
    }
}
// half-row (32 cols from c0) of registers -> hi/lo tiles row r
__device__ __forceinline__ void stageRowHalf(__nv_bfloat16* Th, __nv_bfloat16* Tl,
                                             const float* f, int r, int c0) {
#pragma unroll
    for (int c = 0; c < 32; c += 8) {
        uint4 H, L;
        split8(f + c, H, L);
        *reinterpret_cast<uint4*>(Th + r * LDB + c0 + c) = H;
        *reinterpret_cast<uint4*>(Tl + r * LDB + c0 + c) = L;
    }
}
// half-row of registers -> global hi/lo planes (base includes row, add c0)
__device__ __forceinline__ void storeRowHLHalf(__nv_bfloat16* gH, __nv_bfloat16* gL,
                                               const float* f, int c0) {
#pragma unroll
    for (int c = 0; c < 32; c += 8) {
        uint4 H, L;
        split8(f + c, H, L);
        *reinterpret_cast<uint4*>(gH + c0 + c) = H;
        *reinterpret_cast<uint4*>(gL + c0 + c) = L;
    }
}

// ---------------------------------------------------------------------------
// C(COL-major) = A x B, 3-term bf16 split. Warp mt: rows [mt*16,16), 4 n-tiles.
// ---------------------------------------------------------------------------
template <bool AROW, bool BROW>
__device__ __forceinline__ void wgemm3(const __nv_bfloat16* Ah, const __nv_bfloat16* Al,
                                       const __nv_bfloat16* Bh, const __nv_bfloat16* Bl,
                                       float* C, int mt) {
    using LA = typename std::conditional<AROW, wmma::row_major, wmma::col_major>::type;
    using LB = typename std::conditional<BROW, wmma::row_major, wmma::col_major>::type;
    wmma::fragment<wmma::accumulator, 16, 16, 16, float> c[4];
#pragma unroll
    for (int nt = 0; nt < 4; ++nt) wmma::fill_fragment(c[nt], 0.0f);
    int m0 = mt << 4;
#pragma unroll
    for (int kt = 0; kt < 4; ++kt) {
        int aoff = AROW ? m0 * LDB + (kt << 4) : m0 + (kt << 4) * LDB;
        wmma::fragment<wmma::matrix_a, 16, 16, 16, __nv_bfloat16, LA> ah, al;
        wmma::load_matrix_sync(ah, Ah + aoff, LDB);
        wmma::load_matrix_sync(al, Al + aoff, LDB);
#pragma unroll
        for (int nt = 0; nt < 4; ++nt) {
            int boff = BROW ? (kt << 4) * LDB + (nt << 4) : (kt << 4) + (nt << 4) * LDB;
            wmma::fragment<wmma::matrix_b, 16, 16, 16, __nv_bfloat16, LB> bh, bl;
            wmma::load_matrix_sync(bh, Bh + boff, LDB);
            wmma::load_matrix_sync(bl, Bl + boff, LDB);
            wmma::mma_sync(c[nt], ah, bh, c[nt]);
            wmma::mma_sync(c[nt], ah, bl, c[nt]);
            wmma::mma_sync(c[nt], al, bh, c[nt]);
        }
    }
#pragma unroll
    for (int nt = 0; nt < 4; ++nt)
        wmma::store_matrix_sync(C + m0 + (nt << 4) * LDC, c[nt], LDC,
                                wmma::mem_col_major);
}

// ---------------------------------------------------------------------------
__global__ void qmean_kernel(const float* __restrict__ Q) {
    int bid = blockIdx.x;
    int bh = bid >> 4;
    int s = ((bid & 15) << 2) + (threadIdx.x >> 6);
    int d = threadIdx.x & 63;
    const float* base = Q + bh * 262144 + s * 64 + d;
    float acc = 0.f;
#pragma unroll 16
    for (int i = 0; i < 64; ++i) acc += base[i * 4096];
    acc *= (1.0f / 64.0f);
    float h = __bfloat162float(__float2bfloat16(acc));
    int o = (bh << 6 | s) * 64 + d;
    g_qmeanH[o] = __float2bfloat16(acc);
    g_qmeanL[o] = __float2bfloat16(acc - h);
}

// ---------------------------------------------------------------------------
// B: per (bh,j): S=scale*qbar_j K^T; R=softmax_t; ent; kbar=R K; (vbar=R V)
// grid 4096, 128 thr
// ---------------------------------------------------------------------------
__global__ void __launch_bounds__(128)
bstep_kernel(const float* __restrict__ Kg, const float* __restrict__ Vg,
             int use_qmean, int do_vbar) {
    int bid = blockIdx.x, bh = bid >> 6, j = bid & 63;
    extern __shared__ char sm[];
    __nv_bfloat16* Ah = (__nv_bfloat16*)(sm + OFF_AH);   // qbar -> R
    __nv_bfloat16* Al = (__nv_bfloat16*)(sm + OFF_AL);
    __nv_bfloat16* Kh = (__nv_bfloat16*)(sm + OFF_BH);
    __nv_bfloat16* Kl = (__nv_bfloat16*)(sm + OFF_BL);
    __nv_bfloat16* Vh = (__nv_bfloat16*)(sm + OFF_VH);
    __nv_bfloat16* Vl = (__nv_bfloat16*)(sm + OFF_VL);
    float* C = (float*)(sm + OFF_C);
    int tid = threadIdx.x, wid = tid >> 5;
    int r = tid >> 1, half = tid & 1, c0 = half << 5;   // pair decomposition

    int qoff = use_qmean ? (bh << 12) : (bh * 262144 + j * 4096);
    copyTile(smem_u32(Ah), (use_qmean ? g_qmeanH : g_qbarH) + qoff, tid);
    copyTile(smem_u32(Al), (use_qmean ? g_qmeanL : g_qbarL) + qoff, tid);
    cpa_commit();
    stageHL(Kh, Kl, Kg + bh * 262144 + j * 4096, 64, tid);
    if (do_vbar) stageHL(Vh, Vl, Vg + bh * 262144 + j * 4096, 64, tid);
    cpa_waitg<0>();
    __syncthreads();

    // GEMM1: S[s][t] = qbar(s,d).K(t,d); C col-major
    wgemm3<true, false>(Ah, Al, Kh, Kl, C, wid);
    __syncthreads();

    // softmax over t: 2 threads per row s=r, 32 cols each, log-free entropy
    {
        float g[32], f[32], mx = -1e30f;
#pragma unroll
        for (int c = 0; c < 32; ++c) {
            g[c] = C[(c0 + c) * LDC + r] * SCALE;
            mx = fmaxf(mx, g[c]);
        }
        mx = fmaxf(mx, __shfl_xor_sync(0xffffffffu, mx, 1));
        float sum = 0.f, es = 0.f;
#pragma unroll
        for (int c = 0; c < 32; ++c) {
            g[c] -= mx;
            f[c] = __expf(g[c]);
            sum += f[c];
            es += f[c] * g[c];
        }
        sum += __shfl_xor_sync(0xffffffffu, sum, 1);
        es += __shfl_xor_sync(0xffffffffu, es, 1);
        float inv = 1.0f / sum;
        if (half == 0)
            g_ent[((bh << 6) + r) * 64 + j] = __logf(sum) - es * inv;
#pragma unroll
        for (int c = 0; c < 32; ++c) f[c] *= inv;
        stageRowHalf(Ah, Al, f, r, c0);       // R replaces qbar
    }
    __syncthreads();

    // GEMM2: kbar = R(s,t) K(t,d)
    wgemm3<true, true>(Ah, Al, Kh, Kl, C, wid);
    __syncthreads();
    {
        float f[32];
#pragma unroll
        for (int c = 0; c < 32; ++c) f[c] = C[(c0 + c) * LDC + r];
        int o = bh * 262144 + r * 4096 + (j << 6);
        storeRowHLHalf(g_kbarH + o, g_kbarL + o, f, c0);
    }
    if (do_vbar) {
        __syncthreads();
        wgemm3<true, true>(Ah, Al, Vh, Vl, C, wid);
        __syncthreads();
        float f[32];
#pragma unroll
        for (int c = 0; c < 32; ++c) f[c] = C[(c0 + c) * LDC + r];
        int o = bh * 262144 + r * 4096 + (j << 6);
        storeRowHLHalf(g_vbarH + o, g_vbarL + o, f, c0);
    }
}

// ---------------------------------------------------------------------------
// C (fused): per (bh,s): SL = scale*Q kbar^T + ent; L = softmax_j
//   non-final: qbar[j][d] = (sum_i L[i][j] Q[i][d]) / (sum_i L[i][j])
//   final:     out[i][d] = sum_j L[i][j] vbar[j][d]
// grid 4096, 128 thr
// ---------------------------------------------------------------------------
__global__ void __launch_bounds__(128)
cstep_kernel(const float* __restrict__ Qg, float* __restrict__ out, int is_final) {
    int bid = blockIdx.x, bh = bid >> 6, s = bid & 63;
    extern __shared__ char sm[];
    __nv_bfloat16* Qh = (__nv_bfloat16*)(sm + OFF_AH);
    __nv_bfloat16* Ql = (__nv_bfloat16*)(sm + OFF_AL);
    __nv_bfloat16* Bh = (__nv_bfloat16*)(sm + OFF_BH);  // kbar -> L
    __nv_bfloat16* Bl = (__nv_bfloat16*)(sm + OFF_BL);
    __nv_bfloat16* Vh = (__nv_bfloat16*)(sm + OFF_VH);
    __nv_bfloat16* Vl = (__nv_bfloat16*)(sm + OFF_VL);
    float* C = (float*)(sm + OFF_C);
    float* sEnt = (float*)(sm + OFF_W);
    float* sW = sEnt + 64;
    int tid = threadIdx.x, wid = tid >> 5;
    int r = tid >> 1, half = tid & 1, c0 = half << 5;

    int koff = bh * 262144 + s * 4096;
    copyTile(smem_u32(Bh), g_kbarH + koff, tid);
    copyTile(smem_u32(Bl), g_kbarL + koff, tid);
    cpa_commit();
    if (is_final) {
        copyTile(smem_u32(Vh), g_vbarH + koff, tid);
        copyTile(smem_u32(Vl), g_vbarL + koff, tid);
        cpa_commit();
    }
    stageHL(Qh, Ql, Qg + bh * 262144 + s * 64, 4096, tid);
    if (tid < 64) sEnt[tid] = g_ent[((bh << 6) + s) * 64 + tid];
    if (is_final) cpa_waitg<1>(); else cpa_waitg<0>();   // vbar may stay in flight
    __syncthreads();

    // GEMM1: SL[i][j] = Q(i,d).kbar(j,d)
    wgemm3<true, false>(Qh, Ql, Bh, Bl, C, wid);
    __syncthreads();

    // softmax over j: 2 threads per row i=r
    {
        float f[32], mx = -1e30f;
#pragma unroll
        for (int c = 0; c < 32; ++c) {
            f[c] = C[(c0 + c) * LDC + r] * SCALE + sEnt[c0 + c];
            mx = fmaxf(mx, f[c]);
        }
        mx = fmaxf(mx, __shfl_xor_sync(0xffffffffu, mx, 1));
        float sum = 0.f;
#pragma unroll
        for (int c = 0; c < 32; ++c) { f[c] = __expf(f[c] - mx); sum += f[c]; }
        sum += __shfl_xor_sync(0xffffffffu, sum, 1);
        float inv = 1.0f / sum;
#pragma unroll
        for (int c = 0; c < 32; ++c) f[c] *= inv;    // L row r, cols [c0,c0+32)
        stageRowHalf(Bh, Bl, f, r, c0);               // L replaces kbar
        if (!is_final) {
#pragma unroll
            for (int c = 0; c < 32; ++c) C[(c0 + c) * LDC + r] = f[c];
        }
    }
    __syncthreads();

    if (!is_final) {
        if (tid < 64) {    // w_j = sum_i L[i][j], rotated conflict-free
            int jj = tid;
            float w = 0.f;
#pragma unroll 8
            for (int i = 0; i < 64; ++i) w += C[jj * LDC + ((i + jj) & 63)];
            sW[jj] = 1.0f / w;
        }
        __syncthreads();
        // qbar_num(j,d) = sum_i L(i,j) Q(i,d): A = L col view, B = Q row
        wgemm3<false, true>(Bh, Bl, Qh, Ql, C, wid);
        __syncthreads();
        {
            float iw = sW[r];
            float f[32];
#pragma unroll
            for (int c = 0; c < 32; ++c) f[c] = C[(c0 + c) * LDC + r] * iw;
            int o = bh * 262144 + r * 4096 + (s << 6);
            storeRowHLHalf(g_qbarH + o, g_qbarL + o, f, c0);
        }
    } else {
        cpa_waitg<0>();    // vbar tiles now needed
        __syncthreads();
        // out(i,d) = sum_j L(i,j) vbar(j,d)
        wgemm3<true, true>(Bh, Bl, Vh, Vl, C, wid);
        __syncthreads();
        {
            float* o = out + bh * 262144 + r * 4096 + (s << 6) + c0;
#pragma unroll
            for (int c = 0; c < 32; c += 4)
                *reinterpret_cast<float4*>(o + c) =
                    make_float4(C[(c0 + c) * LDC + r], C[(c0 + c + 1) * LDC + r],
                                C[(c0 + c + 2) * LDC + r], C[(c0 + c + 3) * LDC + r]);
        }
    }
}

// ---------------------------------------------------------------------------
extern "C" void kernel_launch(void* const* d_in, const int* in_sizes, int n_in,
                              void* d_out, int out_size) {
    const float* Q = (const float*)d_in[0];
    const float* K = (const float*)d_in[1];
    const float* V = (const float*)d_in[2];
    float* out = (float*)d_out;

    cudaFuncSetAttribute(bstep_kernel, cudaFuncAttributeMaxDynamicSharedMemorySize, SMEM_BIG);
    cudaFuncSetAttribute(cstep_kernel, cudaFuncAttributeMaxDynamicSharedMemorySize, SMEM_BIG);

    // step 0 (uniform L -> qbar == per-s mean of Q)
    qmean_kernel<<<1024, 256>>>(Q);
    bstep_kernel<<<4096, 128, SMEM_SMALL>>>(K, V, 1, 0);
    cstep_kernel<<<4096, 128, SMEM_SMALL>>>(Q, out, 0);
    // step 1
    bstep_kernel<<<4096, 128, SMEM_SMALL>>>(K, V, 0, 0);
    cstep_kernel<<<4096, 128, SMEM_SMALL>>>(Q, out, 0);
    // step 2
    bstep_kernel<<<4096, 128, SMEM_BIG>>>(K, V, 0, 1);   // + vbar
    cstep_kernel<<<4096, 128, SMEM_BIG>>>(Q, out, 1);    // final: out = L vbar
}

// round 15
// speedup vs baseline: 1.5232x; 1.1761x over previous
#include <cuda_runtime.h>
#include <cuda_bf16.h>
#include <mma.h>
#include <type_traits>

// MonarchAttention on GB300 — v7b: bstep FA2-style hand-rolled mma.sync
// (register-resident softmax, S-acc -> A-frag reuse, no C buffer, 1 barrier,
// 36.9KB smem). cstep = v6 WMMA. Fixes v7's asm operand-index typo.
// B=4,H=16 -> BH=64; N=4096, D=64, b=m=64, STEPS=3.

using namespace nvcuda;
typedef unsigned int u32;

#define SCALE 0.125f
#define LDB 72   // bf16 tile row stride (144B)
#define LDC 68   // f32 C stride (cstep), COL-major

// cstep smem offsets (v6)
#define OFF_AH 0
#define OFF_AL 9216
#define OFF_BH 18432
#define OFF_BL 27648
#define OFF_C  36864
#define OFF_W  54272
#define OFF_VH 54784
#define OFF_VL 64000
#define SMEM_C_SMALL 54784
#define SMEM_C_BIG   73216
// bstep smem offsets (v7)
#define BO_VH 36864
#define BO_VL 46080
#define SMEM_B_SMALL 36864
#define SMEM_B_BIG   55296

__device__ float g_ent[262144];                 // [bh][s][j]
__device__ __nv_bfloat16 g_qmeanH[262144], g_qmeanL[262144];
__device__ __nv_bfloat16 g_qbarH[16777216], g_qbarL[16777216];  // [bh][j][s][d]
__device__ __nv_bfloat16 g_kbarH[16777216], g_kbarL[16777216];  // [bh][s][j][d]
__device__ __nv_bfloat16 g_vbarH[16777216], g_vbarL[16777216];  // [bh][s][j][d]

// ---------------------------------------------------------------------------
__device__ __forceinline__ u32 smem_u32(const void* p) {
    u32 a;
    asm("{ .reg .u64 t; cvta.to.shared.u64 t, %1; cvt.u32.u64 %0, t; }"
        : "=r"(a) : "l"(p));
    return a;
}
__device__ __forceinline__ void cpa16(u32 s, const void* g) {
    asm volatile("cp.async.cg.shared.global [%0], [%1], 16;" :: "r"(s), "l"(g));
}
__device__ __forceinline__ void cpa_commit() {
    asm volatile("cp.async.commit_group;" ::: "memory");
}
template <int N>
__device__ __forceinline__ void cpa_waitg() {
    asm volatile("cp.async.wait_group %0;" :: "n"(N) : "memory");
}
__device__ __forceinline__ u32 pack2(float a, float b) {
    return (u32)__bfloat16_as_ushort(__float2bfloat16(a)) |
           ((u32)__bfloat16_as_ushort(__float2bfloat16(b)) << 16);
}
__device__ __forceinline__ void split8(const float* v, uint4& H, uint4& L) {
    float h[8];
#pragma unroll
    for (int i = 0; i < 8; ++i) h[i] = __bfloat162float(__float2bfloat16(v[i]));
    H = make_uint4(pack2(v[0], v[1]), pack2(v[2], v[3]),
                   pack2(v[4], v[5]), pack2(v[6], v[7]));
    L = make_uint4(pack2(v[0] - h[0], v[1] - h[1]), pack2(v[2] - h[2], v[3] - h[3]),
                   pack2(v[4] - h[4], v[5] - h[5]), pack2(v[6] - h[6], v[7] - h[7]));
}
// hi/lo pair store: 2 f32 -> one u32 in each bf16 plane
__device__ __forceinline__ void stPair(__nv_bfloat16* gH, __nv_bfloat16* gL,
                                       float x, float y) {
    float hx = __bfloat162float(__float2bfloat16(x));
    float hy = __bfloat162float(__float2bfloat16(y));
    *reinterpret_cast<u32*>(gH) = pack2(x, y);
    *reinterpret_cast<u32*>(gL) = pack2(x - hx, y - hy);
}

// fp32 64x64 (row stride rs) -> split hi/lo tiles (row-major LDB). 128 thr.
__device__ __forceinline__ void stageHL(__nv_bfloat16* Th, __nv_bfloat16* Tl,
                                        const float* src, int rs, int tid) {
#pragma unroll
    for (int it = 0; it < 8; ++it) {
        int lin = it * 128 + tid;
        int r = lin >> 4, c4 = (lin & 15) << 2;
        float4 v = *reinterpret_cast<const float4*>(src + r * rs + c4);
        float h0 = __bfloat162float(__float2bfloat16(v.x));
        float h1 = __bfloat162float(__float2bfloat16(v.y));
        float h2 = __bfloat162float(__float2bfloat16(v.z));
        float h3 = __bfloat162float(__float2bfloat16(v.w));
        *reinterpret_cast<uint2*>(Th + r * LDB + c4) =
            make_uint2(pack2(v.x, v.y), pack2(v.z, v.w));
        *reinterpret_cast<uint2*>(Tl + r * LDB + c4) =
            make_uint2(pack2(v.x - h0, v.y - h1), pack2(v.z - h2, v.w - h3));
    }
}
// pre-split plane (64x64 bf16 contiguous) -> tile via cp.async. 128 thr.
__device__ __forceinline__ void copyTile(u32 sbase, const __nv_bfloat16* g, int tid) {
#pragma unroll
    for (int it = 0; it < 4; ++it) {
        int idx = it * 128 + tid;
        int row = idx >> 3, ch = idx & 7;
        cpa16(sbase + row * 144 + ch * 16, g + row * 64 + ch * 8);
    }
}
__device__ __forceinline__ void stageRowHalf(__nv_bfloat16* Th, __nv_bfloat16* Tl,
                                             const float* f, int r, int c0) {
#pragma unroll
    for (int c = 0; c < 32; c += 8) {
        uint4 H, L;
        split8(f + c, H, L);
        *reinterpret_cast<uint4*>(Th + r * LDB + c0 + c) = H;
        *reinterpret_cast<uint4*>(Tl + r * LDB + c0 + c) = L;
    }
}
__device__ __forceinline__ void storeRowHLHalf(__nv_bfloat16* gH, __nv_bfloat16* gL,
                                               const float* f, int c0) {
#pragma unroll
    for (int c = 0; c < 32; c += 8) {
        uint4 H, L;
        split8(f + c, H, L);
        *reinterpret_cast<uint4*>(gH + c0 + c) = H;
        *reinterpret_cast<uint4*>(gL + c0 + c) = L;
    }
}

// ---------------------------------------------------------------------------
// mma.sync / ldmatrix primitives
// ---------------------------------------------------------------------------
__device__ __forceinline__ void mma16816(float* c, const u32* a, const u32* b) {
    asm volatile(
        "mma.sync.aligned.m16n8k16.row.col.f32.bf16.bf16.f32 "
        "{%0,%1,%2,%3}, {%4,%5,%6,%7}, {%8,%9}, {%0,%1,%2,%3};"
        : "+f"(c[0]), "+f"(c[1]), "+f"(c[2]), "+f"(c[3])
        : "r"(a[0]), "r"(a[1]), "r"(a[2]), "r"(a[3]), "r"(b[0]), "r"(b[1]));
}
__device__ __forceinline__ void ldsm4(u32 addr, u32* r) {
    asm volatile("ldmatrix.sync.aligned.m8n8.x4.shared.b16 {%0,%1,%2,%3}, [%4];"
                 : "=r"(r[0]), "=r"(r[1]), "=r"(r[2]), "=r"(r[3]) : "r"(addr));
}
__device__ __forceinline__ void ldsm2(u32 addr, u32* r) {
    asm volatile("ldmatrix.sync.aligned.m8n8.x2.shared.b16 {%0,%1}, [%2];"
                 : "=r"(r[0]), "=r"(r[1]) : "r"(addr));
}
__device__ __forceinline__ void ldsm2t(u32 addr, u32* r) {
    asm volatile("ldmatrix.sync.aligned.m8n8.x2.trans.shared.b16 {%0,%1}, [%2];"
                 : "=r"(r[0]), "=r"(r[1]) : "r"(addr));
}

// ---------------------------------------------------------------------------
__global__ void qmean_kernel(const float* __restrict__ Q) {
    int bid = blockIdx.x;
    int bh = bid >> 4;
    int s = ((bid & 15) << 2) + (threadIdx.x >> 6);
    int d = threadIdx.x & 63;
    const float* base = Q + bh * 262144 + s * 64 + d;
    float acc = 0.f;
#pragma unroll 16
    for (int i = 0; i < 64; ++i) acc += base[i * 4096];
    acc *= (1.0f / 64.0f);
    float h = __bfloat162float(__float2bfloat16(acc));
    int o = (bh << 6 | s) * 64 + d;
    g_qmeanH[o] = __float2bfloat16(acc);
    g_qmeanL[o] = __float2bfloat16(acc - h);
}

// ---------------------------------------------------------------------------
// bstep v7: hand-rolled mma. per (bh,j):
//   S = scale*qbar K^T; R=softmax_t(S)+ent (registers); kbar=R K; (vbar=R V)
// grid 4096, 128 thr, 1 barrier.
// ---------------------------------------------------------------------------
__global__ void __launch_bounds__(128)
bstep_kernel(const float* __restrict__ Kg, const float* __restrict__ Vg,
             int use_qmean, int do_vbar) {
    int bid = blockIdx.x, bh = bid >> 6, j = bid & 63;
    extern __shared__ char sm[];
    __nv_bfloat16* Ah = (__nv_bfloat16*)(sm + OFF_AH);
    __nv_bfloat16* Al = (__nv_bfloat16*)(sm + OFF_AL);
    __nv_bfloat16* Kh = (__nv_bfloat16*)(sm + OFF_BH);
    __nv_bfloat16* Kl = (__nv_bfloat16*)(sm + OFF_BL);
    __nv_bfloat16* Vh = (__nv_bfloat16*)(sm + BO_VH);
    __nv_bfloat16* Vl = (__nv_bfloat16*)(sm + BO_VL);
    int tid = threadIdx.x, w = tid >> 5, lane = tid & 31;
    int g = lane >> 2, tq = lane & 3;

    int qoff = use_qmean ? (bh << 12) : (bh * 262144 + j * 4096);
    copyTile(smem_u32(Ah), (use_qmean ? g_qmeanH : g_qbarH) + qoff, tid);
    copyTile(smem_u32(Al), (use_qmean ? g_qmeanL : g_qbarL) + qoff, tid);
    cpa_commit();
    stageHL(Kh, Kl, Kg + bh * 262144 + j * 4096, 64, tid);
    if (do_vbar) stageHL(Vh, Vl, Vg + bh * 262144 + j * 4096, 64, tid);
    cpa_waitg<0>();
    __syncthreads();

    u32 bAh = smem_u32(Ah), bAl = smem_u32(Al);
    u32 bKh = smem_u32(Kh), bKl = smem_u32(Kl);

    // ldmatrix lane-address components
    int l15 = lane & 15;
    // A (m16k16 at m0=16w, k0): mats (m0,k0)(m8,k0)(m0,k8)(m8,k8)
    int arow = 16 * w + ((lane >> 3) & 1) * 8 + (lane & 7);
    int aext = (lane >> 4) * 8;
    // B1 non-trans (tile rows = n (t), cols = k (d)): mats (n0,k0)(n0,k8)
    int b1row = l15 & 7, b1ext = (l15 >> 3) * 8;
    // B2 trans (tile rows = k (t), cols = n (d)): mats (k0,n0)(k8,n0)
    int b2row = (l15 >> 3) * 8 + (l15 & 7);

    // ---------------- GEMM1: S[s][t] ----------------
    float S[8][4];
#pragma unroll
    for (int nt = 0; nt < 8; ++nt)
#pragma unroll
        for (int c = 0; c < 4; ++c) S[nt][c] = 0.f;

#pragma unroll
    for (int kt = 0; kt < 4; ++kt) {
        int k0 = kt << 4;
        u32 ah[4], al[4], b_h[2], b_l[2];
        u32 aoff = (u32)((arow * LDB + k0 + aext) * 2);
        ldsm4(bAh + aoff, ah);
        ldsm4(bAl + aoff, al);
#pragma unroll
        for (int nt = 0; nt < 8; ++nt) {
            u32 boff = (u32)(((nt * 8 + b1row) * LDB + k0 + b1ext) * 2);
            ldsm2(bKh + boff, b_h);
            ldsm2(bKl + boff, b_l);
            mma16816(S[nt], ah, b_h);
            mma16816(S[nt], ah, b_l);
            mma16816(S[nt], al, b_h);
        }
    }

    // ---------------- softmax + entropy (registers) ----------------
    // rows: rA = 16w+g (S[nt][0..1]), rB = 16w+8+g (S[nt][2..3])
    {
        float mx0 = -1e30f, mx1 = -1e30f;
#pragma unroll
        for (int nt = 0; nt < 8; ++nt) {
            S[nt][0] *= SCALE; S[nt][1] *= SCALE;
            S[nt][2] *= SCALE; S[nt][3] *= SCALE;
            mx0 = fmaxf(mx0, fmaxf(S[nt][0], S[nt][1]));
            mx1 = fmaxf(mx1, fmaxf(S[nt][2], S[nt][3]));
        }
        mx0 = fmaxf(mx0, __shfl_xor_sync(0xffffffffu, mx0, 1));
        mx0 = fmaxf(mx0, __shfl_xor_sync(0xffffffffu, mx0, 2));
        mx1 = fmaxf(mx1, __shfl_xor_sync(0xffffffffu, mx1, 1));
        mx1 = fmaxf(mx1, __shfl_xor_sync(0xffffffffu, mx1, 2));
        float s0 = 0.f, s1 = 0.f, e0 = 0.f, e1 = 0.f;
#pragma unroll
        for (int nt = 0; nt < 8; ++nt) {
            float g0 = S[nt][0] - mx0, g1 = S[nt][1] - mx0;
            float g2 = S[nt][2] - mx1, g3 = S[nt][3] - mx1;
            float f0 = __expf(g0), f1 = __expf(g1);
            float f2 = __expf(g2), f3 = __expf(g3);
            s0 += f0 + f1; s1 += f2 + f3;
            e0 += f0 * g0 + f1 * g1; e1 += f2 * g2 + f3 * g3;
            S[nt][0] = f0; S[nt][1] = f1; S[nt][2] = f2; S[nt][3] = f3;
        }
        s0 += __shfl_xor_sync(0xffffffffu, s0, 1);
        s0 += __shfl_xor_sync(0xffffffffu, s0, 2);
        s1 += __shfl_xor_sync(0xffffffffu, s1, 1);
        s1 += __shfl_xor_sync(0xffffffffu, s1, 2);
        e0 += __shfl_xor_sync(0xffffffffu, e0, 1);
        e0 += __shfl_xor_sync(0xffffffffu, e0, 2);
        e1 += __shfl_xor_sync(0xffffffffu, e1, 1);
        e1 += __shfl_xor_sync(0xffffffffu, e1, 2);
        float i0 = 1.0f / s0, i1 = 1.0f / s1;
        if (tq == 0) {
            g_ent[((bh << 6) + 16 * w + g) * 64 + j] = __logf(s0) - e0 * i0;
            g_ent[((bh << 6) + 16 * w + 8 + g) * 64 + j] = __logf(s1) - e1 * i1;
        }
#pragma unroll
        for (int nt = 0; nt < 8; ++nt) {
            S[nt][0] *= i0; S[nt][1] *= i0;
            S[nt][2] *= i1; S[nt][3] *= i1;
        }
    }

    // ---------------- R -> A fragments (hi/lo, registers) ----------------
    u32 Rh[4][4], Rl[4][4];
#pragma unroll
    for (int kt = 0; kt < 4; ++kt) {
        const float* e = S[2 * kt];
        const float* o = S[2 * kt + 1];
        float h;
        Rh[kt][0] = pack2(e[0], e[1]);
        Rh[kt][1] = pack2(e[2], e[3]);
        Rh[kt][2] = pack2(o[0], o[1]);
        Rh[kt][3] = pack2(o[2], o[3]);
        float r0, r1, r2, r3;
        h = __bfloat162float(__float2bfloat16(e[0])); r0 = e[0] - h;
        h = __bfloat162float(__float2bfloat16(e[1])); r1 = e[1] - h;
        h = __bfloat162float(__float2bfloat16(e[2])); r2 = e[2] - h;
        h = __bfloat162float(__float2bfloat16(e[3])); r3 = e[3] - h;
        Rl[kt][0] = pack2(r0, r1);
        Rl[kt][1] = pack2(r2, r3);
        h = __bfloat162float(__float2bfloat16(o[0])); r0 = o[0] - h;
        h = __bfloat162float(__float2bfloat16(o[1])); r1 = o[1] - h;
        h = __bfloat162float(__float2bfloat16(o[2])); r2 = o[2] - h;
        h = __bfloat162float(__float2bfloat16(o[3])); r3 = o[3] - h;
        Rl[kt][2] = pack2(r0, r1);
        Rl[kt][3] = pack2(r2, r3);
    }

    // ---------------- GEMM2: kbar = R K ----------------
    {
        float KB[8][4];
#pragma unroll
        for (int nt = 0; nt < 8; ++nt)
#pragma unroll
            for (int c = 0; c < 4; ++c) KB[nt][c] = 0.f;
#pragma unroll
        for (int kt = 0; kt < 4; ++kt) {
#pragma unroll
            for (int nt = 0; nt < 8; ++nt) {
                u32 boff = (u32)(((kt * 16 + b2row) * LDB + nt * 8) * 2);
                u32 b_h[2], b_l[2];
                ldsm2t(bKh + boff, b_h);
                ldsm2t(bKl + boff, b_l);
                mma16816(KB[nt], Rh[kt], b_h);
                mma16816(KB[nt], Rh[kt], b_l);
                mma16816(KB[nt], Rl[kt], b_h);
            }
        }
        long o0 = (long)bh * 262144 + (16 * w + g) * 4096 + j * 64;
        long o1 = o0 + 8 * 4096;
#pragma unroll
        for (int nt = 0; nt < 8; ++nt) {
            int d = nt * 8 + 2 * tq;
            stPair(g_kbarH + o0 + d, g_kbarL + o0 + d, KB[nt][0], KB[nt][1]);
            stPair(g_kbarH + o1 + d, g_kbarL + o1 + d, KB[nt][2], KB[nt][3]);
        }
    }

    // ---------------- GEMM3: vbar = R V (final step only) ----------------
    if (do_vbar) {
        u32 bVh = smem_u32(Vh), bVl = smem_u32(Vl);
        float VB[8][4];
#pragma unroll
        for (int nt = 0; nt < 8; ++nt)
#pragma unroll
            for (int c = 0; c < 4; ++c) VB[nt][c] = 0.f;
#pragma unroll
        for (int kt = 0; kt < 4; ++kt) {
#pragma unroll
            for (int nt = 0; nt < 8; ++nt) {
                u32 boff = (u32)(((kt * 16 + b2row) * LDB + nt * 8) * 2);
                u32 b_h[2], b_l[2];
                ldsm2t(bVh + boff, b_h);
                ldsm2t(bVl + boff, b_l);
                mma16816(VB[nt], Rh[kt], b_h);
                mma16816(VB[nt], Rh[kt], b_l);
                mma16816(VB[nt], Rl[kt], b_h);
            }
        }
        long o0 = (long)bh * 262144 + (16 * w + g) * 4096 + j * 64;
        long o1 = o0 + 8 * 4096;
#pragma unroll
        for (int nt = 0; nt < 8; ++nt) {
            int d = nt * 8 + 2 * tq;
            stPair(g_vbarH + o0 + d, g_vbarL + o0 + d, VB[nt][0], VB[nt][1]);
            stPair(g_vbarH + o1 + d, g_vbarL + o1 + d, VB[nt][2], VB[nt][3]);
        }
    }
}

// ---------------------------------------------------------------------------
// cstep (v6, unchanged): WMMA 3-term split.
// ---------------------------------------------------------------------------
template <bool AROW, bool BROW>
__device__ __forceinline__ void wgemm3(const __nv_bfloat16* Ah, const __nv_bfloat16* Al,
                                       const __nv_bfloat16* Bh, const __nv_bfloat16* Bl,
                                       float* C, int mt) {
    using LA = typename std::conditional<AROW, wmma::row_major, wmma::col_major>::type;
    using LB = typename std::conditional<BROW, wmma::row_major, wmma::col_major>::type;
    wmma::fragment<wmma::accumulator, 16, 16, 16, float> c[4];
#pragma unroll
    for (int nt = 0; nt < 4; ++nt) wmma::fill_fragment(c[nt], 0.0f);
    int m0 = mt << 4;
#pragma unroll
    for (int kt = 0; kt < 4; ++kt) {
        int aoff = AROW ? m0 * LDB + (kt << 4) : m0 + (kt << 4) * LDB;
        wmma::fragment<wmma::matrix_a, 16, 16, 16, __nv_bfloat16, LA> ah, al;
        wmma::load_matrix_sync(ah, Ah + aoff, LDB);
        wmma::load_matrix_sync(al, Al + aoff, LDB);
#pragma unroll
        for (int nt = 0; nt < 4; ++nt) {
            int boff = BROW ? (kt << 4) * LDB + (nt << 4) : (kt << 4) + (nt << 4) * LDB;
            wmma::fragment<wmma::matrix_b, 16, 16, 16, __nv_bfloat16, LB> bh, bl;
            wmma::load_matrix_sync(bh, Bh + boff, LDB);
            wmma::load_matrix_sync(bl, Bl + boff, LDB);
            wmma::mma_sync(c[nt], ah, bh, c[nt]);
            wmma::mma_sync(c[nt], ah, bl, c[nt]);
            wmma::mma_sync(c[nt], al, bh, c[nt]);
        }
    }
#pragma unroll
    for (int nt = 0; nt < 4; ++nt)
        wmma::store_matrix_sync(C + m0 + (nt << 4) * LDC, c[nt], LDC,
                                wmma::mem_col_major);
}

__global__ void __launch_bounds__(128)
cstep_kernel(const float* __restrict__ Qg, float* __restrict__ out, int is_final) {
    int bid = blockIdx.x, bh = bid >> 6, s = bid & 63;
    extern __shared__ char sm[];
    __nv_bfloat16* Qh = (__nv_bfloat16*)(sm + OFF_AH);
    __nv_bfloat16* Ql = (__nv_bfloat16*)(sm + OFF_AL);
    __nv_bfloat16* Bh = (__nv_bfloat16*)(sm + OFF_BH);
    __nv_bfloat16* Bl = (__nv_bfloat16*)(sm + OFF_BL);
    __nv_bfloat16* Vh = (__nv_bfloat16*)(sm + OFF_VH);
    __nv_bfloat16* Vl = (__nv_bfloat16*)(sm + OFF_VL);
    float* C = (float*)(sm + OFF_C);
    float* sEnt = (float*)(sm + OFF_W);
    float* sW = sEnt + 64;
    int tid = threadIdx.x, wid = tid >> 5;
    int r = tid >> 1, half = tid & 1, c0 = half << 5;

    int koff = bh * 262144 + s * 4096;
    copyTile(smem_u32(Bh), g_kbarH + koff, tid);
    copyTile(smem_u32(Bl), g_kbarL + koff, tid);
    cpa_commit();
    if (is_final) {
        copyTile(smem_u32(Vh), g_vbarH + koff, tid);
        copyTile(smem_u32(Vl), g_vbarL + koff, tid);
        cpa_commit();
    }
    stageHL(Qh, Ql, Qg + bh * 262144 + s * 64, 4096, tid);
    if (tid < 64) sEnt[tid] = g_ent[((bh << 6) + s) * 64 + tid];
    if (is_final) cpa_waitg<1>(); else cpa_waitg<0>();
    __syncthreads();

    wgemm3<true, false>(Qh, Ql, Bh, Bl, C, wid);
    __syncthreads();

    {
        float f[32], mx = -1e30f;
#pragma unroll
        for (int c = 0; c < 32; ++c) {
            f[c] = C[(c0 + c) * LDC + r] * SCALE + sEnt[c0 + c];
            mx = fmaxf(mx, f[c]);
        }
        mx = fmaxf(mx, __shfl_xor_sync(0xffffffffu, mx, 1));
        float sum = 0.f;
#pragma unroll
        for (int c = 0; c < 32; ++c) { f[c] = __expf(f[c] - mx); sum += f[c]; }
        sum += __shfl_xor_sync(0xffffffffu, sum, 1);
        float inv = 1.0f / sum;
#pragma unroll
        for (int c = 0; c < 32; ++c) f[c] *= inv;
        stageRowHalf(Bh, Bl, f, r, c0);
        if (!is_final) {
#pragma unroll
            for (int c = 0; c < 32; ++c) C[(c0 + c) * LDC + r] = f[c];
        }
    }
    __syncthreads();

    if (!is_final) {
        if (tid < 64) {
            int jj = tid;
            float w = 0.f;
#pragma unroll 8
            for (int i = 0; i < 64; ++i) w += C[jj * LDC + ((i + jj) & 63)];
            sW[jj] = 1.0f / w;
        }
        __syncthreads();
        wgemm3<false, true>(Bh, Bl, Qh, Ql, C, wid);
        __syncthreads();
        {
            float iw = sW[r];
            float f[32];
#pragma unroll
            for (int c = 0; c < 32; ++c) f[c] = C[(c0 + c) * LDC + r] * iw;
            int o = bh * 262144 + r * 4096 + (s << 6);
            storeRowHLHalf(g_qbarH + o, g_qbarL + o, f, c0);
        }
    } else {
        cpa_waitg<0>();
        __syncthreads();
        wgemm3<true, true>(Bh, Bl, Vh, Vl, C, wid);
        __syncthreads();
        {
            float* o = out + bh * 262144 + r * 4096 + (s << 6) + c0;
#pragma unroll
            for (int c = 0; c < 32; c += 4)
                *reinterpret_cast<float4*>(o + c) =
                    make_float4(C[(c0 + c) * LDC + r], C[(c0 + c + 1) * LDC + r],
                                C[(c0 + c + 2) * LDC + r], C[(c0 + c + 3) * LDC + r]);
        }
    }
}

// ---------------------------------------------------------------------------
extern "C" void kernel_launch(void* const* d_in, const int* in_sizes, int n_in,
                              void* d_out, int out_size) {
    const float* Q = (const float*)d_in[0];
    const float* K = (const float*)d_in[1];
    const float* V = (const float*)d_in[2];
    float* out = (float*)d_out;

    cudaFuncSetAttribute(bstep_kernel, cudaFuncAttributeMaxDynamicSharedMemorySize, SMEM_B_BIG);
    cudaFuncSetAttribute(cstep_kernel, cudaFuncAttributeMaxDynamicSharedMemorySize, SMEM_C_BIG);

    // step 0 (uniform L -> qbar == per-s mean of Q)
    qmean_kernel<<<1024, 256>>>(Q);
    bstep_kernel<<<4096, 128, SMEM_B_SMALL>>>(K, V, 1, 0);
    cstep_kernel<<<4096, 128, SMEM_C_SMALL>>>(Q, out, 0);
    // step 1
    bstep_kernel<<<4096, 128, SMEM_B_SMALL>>>(K, V, 0, 0);
    cstep_kernel<<<4096, 128, SMEM_C_SMALL>>>(Q, out, 0);
    // step 2
    bstep_kernel<<<4096, 128, SMEM_B_BIG>>>(K, V, 0, 1);   // + vbar
    cstep_kernel<<<4096, 128, SMEM_C_BIG>>>(Q, out, 1);    // final: out = L vbar
}

// round 16
// speedup vs baseline: 1.9085x; 1.2529x over previous
#include <cuda_runtime.h>
#include <cuda_bf16.h>

// MonarchAttention on GB300 — v8: BOTH kernels FA2-style hand-rolled
// mma.sync.m16n8k16 (register-resident softmax, no C buffer).
// bstep = v7b (validated). cstep: final uses S-acc->A-frag reuse; non-final
// stores L to smem and uses ldmatrix.x4.trans A for the transposed GEMM.
// B=4,H=16 -> BH=64; N=4096, D=64, b=m=64, STEPS=3.

typedef unsigned int u32;

#define SCALE 0.125f
#define LDB 72   // bf16 tile row stride (144B)

// bstep smem offsets
#define OFF_AH 0
#define OFF_AL 9216
#define OFF_BH 18432
#define OFF_BL 27648
#define BO_VH 36864
#define BO_VL 46080
#define SMEM_B_SMALL 36864
#define SMEM_B_BIG   55296
// cstep smem: Qh 0, Ql 9216, L(kbar) 18432/27648, V 36864/46080
#define SMEM_C_SMALL 37376     // + ent/w at 36864
#define SMEM_C_BIG   55552     // + ent at 55296

__device__ float g_ent[262144];                 // [bh][s][j]
__device__ __nv_bfloat16 g_qmeanH[262144], g_qmeanL[262144];
__device__ __nv_bfloat16 g_qbarH[16777216], g_qbarL[16777216];  // [bh][j][s][d]
__device__ __nv_bfloat16 g_kbarH[16777216], g_kbarL[16777216];  // [bh][s][j][d]
__device__ __nv_bfloat16 g_vbarH[16777216], g_vbarL[16777216];  // [bh][s][j][d]

// ---------------------------------------------------------------------------
__device__ __forceinline__ u32 smem_u32(const void* p) {
    u32 a;
    asm("{ .reg .u64 t; cvta.to.shared.u64 t, %1; cvt.u32.u64 %0, t; }"
        : "=r"(a) : "l"(p));
    return a;
}
__device__ __forceinline__ void cpa16(u32 s, const void* g) {
    asm volatile("cp.async.cg.shared.global [%0], [%1], 16;" :: "r"(s), "l"(g));
}
__device__ __forceinline__ void cpa_commit() {
    asm volatile("cp.async.commit_group;" ::: "memory");
}
template <int N>
__device__ __forceinline__ void cpa_waitg() {
    asm volatile("cp.async.wait_group %0;" :: "n"(N) : "memory");
}
__device__ __forceinline__ u32 pack2(float a, float b) {
    return (u32)__bfloat16_as_ushort(__float2bfloat16(a)) |
           ((u32)__bfloat16_as_ushort(__float2bfloat16(b)) << 16);
}
__device__ __forceinline__ void stPair(__nv_bfloat16* gH, __nv_bfloat16* gL,
                                       float x, float y) {
    float hx = __bfloat162float(__float2bfloat16(x));
    float hy = __bfloat162float(__float2bfloat16(y));
    *reinterpret_cast<u32*>(gH) = pack2(x, y);
    *reinterpret_cast<u32*>(gL) = pack2(x - hx, y - hy);
}

// fp32 64x64 (row stride rs) -> split hi/lo tiles (row-major LDB). 128 thr.
__device__ __forceinline__ void stageHL(__nv_bfloat16* Th, __nv_bfloat16* Tl,
                                        const float* src, int rs, int tid) {
#pragma unroll
    for (int it = 0; it < 8; ++it) {
        int lin = it * 128 + tid;
        int r = lin >> 4, c4 = (lin & 15) << 2;
        float4 v = *reinterpret_cast<const float4*>(src + r * rs + c4);
        float h0 = __bfloat162float(__float2bfloat16(v.x));
        float h1 = __bfloat162float(__float2bfloat16(v.y));
        float h2 = __bfloat162float(__float2bfloat16(v.z));
        float h3 = __bfloat162float(__float2bfloat16(v.w));
        *reinterpret_cast<uint2*>(Th + r * LDB + c4) =
            make_uint2(pack2(v.x, v.y), pack2(v.z, v.w));
        *reinterpret_cast<uint2*>(Tl + r * LDB + c4) =
            make_uint2(pack2(v.x - h0, v.y - h1), pack2(v.z - h2, v.w - h3));
    }
}
// pre-split plane (64x64 bf16 contiguous) -> tile via cp.async. 128 thr.
__device__ __forceinline__ void copyTile(u32 sbase, const __nv_bfloat16* g, int tid) {
#pragma unroll
    for (int it = 0; it < 4; ++it) {
        int idx = it * 128 + tid;
        int row = idx >> 3, ch = idx & 7;
        cpa16(sbase + row * 144 + ch * 16, g + row * 64 + ch * 8);
    }
}

// ---------------------------------------------------------------------------
// mma.sync / ldmatrix primitives
// ---------------------------------------------------------------------------
__device__ __forceinline__ void mma16816(float* c, const u32* a, const u32* b) {
    asm volatile(
        "mma.sync.aligned.m16n8k16.row.col.f32.bf16.bf16.f32 "
        "{%0,%1,%2,%3}, {%4,%5,%6,%7}, {%8,%9}, {%0,%1,%2,%3};"
        : "+f"(c[0]), "+f"(c[1]), "+f"(c[2]), "+f"(c[3])
        : "r"(a[0]), "r"(a[1]), "r"(a[2]), "r"(a[3]), "r"(b[0]), "r"(b[1]));
}
__device__ __forceinline__ void ldsm4(u32 addr, u32* r) {
    asm volatile("ldmatrix.sync.aligned.m8n8.x4.shared.b16 {%0,%1,%2,%3}, [%4];"
                 : "=r"(r[0]), "=r"(r[1]), "=r"(r[2]), "=r"(r[3]) : "r"(addr));
}
__device__ __forceinline__ void ldsm4t(u32 addr, u32* r) {
    asm volatile("ldmatrix.sync.aligned.m8n8.x4.trans.shared.b16 {%0,%1,%2,%3}, [%4];"
                 : "=r"(r[0]), "=r"(r[1]), "=r"(r[2]), "=r"(r[3]) : "r"(addr));
}
__device__ __forceinline__ void ldsm2(u32 addr, u32* r) {
    asm volatile("ldmatrix.sync.aligned.m8n8.x2.shared.b16 {%0,%1}, [%2];"
                 : "=r"(r[0]), "=r"(r[1]) : "r"(addr));
}
__device__ __forceinline__ void ldsm2t(u32 addr, u32* r) {
    asm volatile("ldmatrix.sync.aligned.m8n8.x2.trans.shared.b16 {%0,%1}, [%2];"
                 : "=r"(r[0]), "=r"(r[1]) : "r"(addr));
}

// ---------------------------------------------------------------------------
__global__ void qmean_kernel(const float* __restrict__ Q) {
    int bid = blockIdx.x;
    int bh = bid >> 4;
    int s = ((bid & 15) << 2) + (threadIdx.x >> 6);
    int d = threadIdx.x & 63;
    const float* base = Q + bh * 262144 + s * 64 + d;
    float acc = 0.f;
#pragma unroll 16
    for (int i = 0; i < 64; ++i) acc += base[i * 4096];
    acc *= (1.0f / 64.0f);
    float h = __bfloat162float(__float2bfloat16(acc));
    int o = (bh << 6 | s) * 64 + d;
    g_qmeanH[o] = __float2bfloat16(acc);
    g_qmeanL[o] = __float2bfloat16(acc - h);
}

// ---------------------------------------------------------------------------
// bstep (v7b, validated): per (bh,j):
//   S = scale*qbar K^T; R=softmax_t(S)+ent (registers); kbar=R K; (vbar=R V)
// ---------------------------------------------------------------------------
__global__ void __launch_bounds__(128)
bstep_kernel(const float* __restrict__ Kg, const float* __restrict__ Vg,
             int use_qmean, int do_vbar) {
    int bid = blockIdx.x, bh = bid >> 6, j = bid & 63;
    extern __shared__ char sm[];
    __nv_bfloat16* Ah = (__nv_bfloat16*)(sm + OFF_AH);
    __nv_bfloat16* Al = (__nv_bfloat16*)(sm + OFF_AL);
    __nv_bfloat16* Kh = (__nv_bfloat16*)(sm + OFF_BH);
    __nv_bfloat16* Kl = (__nv_bfloat16*)(sm + OFF_BL);
    __nv_bfloat16* Vh = (__nv_bfloat16*)(sm + BO_VH);
    __nv_bfloat16* Vl = (__nv_bfloat16*)(sm + BO_VL);
    int tid = threadIdx.x, w = tid >> 5, lane = tid & 31;
    int g = lane >> 2, tq = lane & 3;

    int qoff = use_qmean ? (bh << 12) : (bh * 262144 + j * 4096);
    copyTile(smem_u32(Ah), (use_qmean ? g_qmeanH : g_qbarH) + qoff, tid);
    copyTile(smem_u32(Al), (use_qmean ? g_qmeanL : g_qbarL) + qoff, tid);
    cpa_commit();
    stageHL(Kh, Kl, Kg + bh * 262144 + j * 4096, 64, tid);
    if (do_vbar) stageHL(Vh, Vl, Vg + bh * 262144 + j * 4096, 64, tid);
    cpa_waitg<0>();
    __syncthreads();

    u32 bAh = smem_u32(Ah), bAl = smem_u32(Al);
    u32 bKh = smem_u32(Kh), bKl = smem_u32(Kl);

    int l15 = lane & 15;
    int arow = 16 * w + ((lane >> 3) & 1) * 8 + (lane & 7);
    int aext = (lane >> 4) * 8;
    int b1row = l15 & 7, b1ext = (l15 >> 3) * 8;
    int b2row = (l15 >> 3) * 8 + (l15 & 7);

    float S[8][4];
#pragma unroll
    for (int nt = 0; nt < 8; ++nt)
#pragma unroll
        for (int c = 0; c < 4; ++c) S[nt][c] = 0.f;

#pragma unroll
    for (int kt = 0; kt < 4; ++kt) {
        int k0 = kt << 4;
        u32 ah[4], al[4], b_h[2], b_l[2];
        u32 aoff = (u32)((arow * LDB + k0 + aext) * 2);
        ldsm4(bAh + aoff, ah);
        ldsm4(bAl + aoff, al);
#pragma unroll
        for (int nt = 0; nt < 8; ++nt) {
            u32 boff = (u32)(((nt * 8 + b1row) * LDB + k0 + b1ext) * 2);
            ldsm2(bKh + boff, b_h);
            ldsm2(bKl + boff, b_l);
            mma16816(S[nt], ah, b_h);
            mma16816(S[nt], ah, b_l);
            mma16816(S[nt], al, b_h);
        }
    }

    {
        float mx0 = -1e30f, mx1 = -1e30f;
#pragma unroll
        for (int nt = 0; nt < 8; ++nt) {
            S[nt][0] *= SCALE; S[nt][1] *= SCALE;
            S[nt][2] *= SCALE; S[nt][3] *= SCALE;
            mx0 = fmaxf(mx0, fmaxf(S[nt][0], S[nt][1]));
            mx1 = fmaxf(mx1, fmaxf(S[nt][2], S[nt][3]));
        }
        mx0 = fmaxf(mx0, __shfl_xor_sync(0xffffffffu, mx0, 1));
        mx0 = fmaxf(mx0, __shfl_xor_sync(0xffffffffu, mx0, 2));
        mx1 = fmaxf(mx1, __shfl_xor_sync(0xffffffffu, mx1, 1));
        mx1 = fmaxf(mx1, __shfl_xor_sync(0xffffffffu, mx1, 2));
        float s0 = 0.f, s1 = 0.f, e0 = 0.f, e1 = 0.f;
#pragma unroll
        for (int nt = 0; nt < 8; ++nt) {
            float g0 = S[nt][0] - mx0, g1 = S[nt][1] - mx0;
            float g2 = S[nt][2] - mx1, g3 = S[nt][3] - mx1;
            float f0 = __expf(g0), f1 = __expf(g1);
            float f2 = __expf(g2), f3 = __expf(g3);
            s0 += f0 + f1; s1 += f2 + f3;
            e0 += f0 * g0 + f1 * g1; e1 += f2 * g2 + f3 * g3;
            S[nt][0] = f0; S[nt][1] = f1; S[nt][2] = f2; S[nt][3] = f3;
        }
        s0 += __shfl_xor_sync(0xffffffffu, s0, 1);
        s0 += __shfl_xor_sync(0xffffffffu, s0, 2);
        s1 += __shfl_xor_sync(0xffffffffu, s1, 1);
        s1 += __shfl_xor_sync(0xffffffffu, s1, 2);
        e0 += __shfl_xor_sync(0xffffffffu, e0, 1);
        e0 += __shfl_xor_sync(0xffffffffu, e0, 2);
        e1 += __shfl_xor_sync(0xffffffffu, e1, 1);
        e1 += __shfl_xor_sync(0xffffffffu, e1, 2);
        float i0 = 1.0f / s0, i1 = 1.0f / s1;
        if (tq == 0) {
            g_ent[((bh << 6) + 16 * w + g) * 64 + j] = __logf(s0) - e0 * i0;
            g_ent[((bh << 6) + 16 * w + 8 + g) * 64 + j] = __logf(s1) - e1 * i1;
        }
#pragma unroll
        for (int nt = 0; nt < 8; ++nt) {
            S[nt][0] *= i0; S[nt][1] *= i0;
            S[nt][2] *= i1; S[nt][3] *= i1;
        }
    }

    u32 Rh[4][4], Rl[4][4];
#pragma unroll
    for (int kt = 0; kt < 4; ++kt) {
        const float* e = S[2 * kt];
        const float* o = S[2 * kt + 1];
        float h;
        Rh[kt][0] = pack2(e[0], e[1]);
        Rh[kt][1] = pack2(e[2], e[3]);
        Rh[kt][2] = pack2(o[0], o[1]);
        Rh[kt][3] = pack2(o[2], o[3]);
        float r0, r1, r2, r3;
        h = __bfloat162float(__float2bfloat16(e[0])); r0 = e[0] - h;
        h = __bfloat162float(__float2bfloat16(e[1])); r1 = e[1] - h;
        h = __bfloat162float(__float2bfloat16(e[2])); r2 = e[2] - h;
        h = __bfloat162float(__float2bfloat16(e[3])); r3 = e[3] - h;
        Rl[kt][0] = pack2(r0, r1);
        Rl[kt][1] = pack2(r2, r3);
        h = __bfloat162float(__float2bfloat16(o[0])); r0 = o[0] - h;
        h = __bfloat162float(__float2bfloat16(o[1])); r1 = o[1] - h;
        h = __bfloat162float(__float2bfloat16(o[2])); r2 = o[2] - h;
        h = __bfloat162float(__float2bfloat16(o[3])); r3 = o[3] - h;
        Rl[kt][2] = pack2(r0, r1);
        Rl[kt][3] = pack2(r2, r3);
    }

    {
        float KB[8][4];
#pragma unroll
        for (int nt = 0; nt < 8; ++nt)
#pragma unroll
            for (int c = 0; c < 4; ++c) KB[nt][c] = 0.f;
#pragma unroll
        for (int kt = 0; kt < 4; ++kt) {
#pragma unroll
            for (int nt = 0; nt < 8; ++nt) {
                u32 boff = (u32)(((kt * 16 + b2row) * LDB + nt * 8) * 2);
                u32 b_h[2], b_l[2];
                ldsm2t(bKh + boff, b_h);
                ldsm2t(bKl + boff, b_l);
                mma16816(KB[nt], Rh[kt], b_h);
                mma16816(KB[nt], Rh[kt], b_l);
                mma16816(KB[nt], Rl[kt], b_h);
            }
        }
        long o0 = (long)bh * 262144 + (16 * w + g) * 4096 + j * 64;
        long o1 = o0 + 8 * 4096;
#pragma unroll
        for (int nt = 0; nt < 8; ++nt) {
            int d = nt * 8 + 2 * tq;
            stPair(g_kbarH + o0 + d, g_kbarL + o0 + d, KB[nt][0], KB[nt][1]);
            stPair(g_kbarH + o1 + d, g_kbarL + o1 + d, KB[nt][2], KB[nt][3]);
        }
    }

    if (do_vbar) {
        u32 bVh = smem_u32(Vh), bVl = smem_u32(Vl);
        float VB[8][4];
#pragma unroll
        for (int nt = 0; nt < 8; ++nt)
#pragma unroll
            for (int c = 0; c < 4; ++c) VB[nt][c] = 0.f;
#pragma unroll
        for (int kt = 0; kt < 4; ++kt) {
#pragma unroll
            for (int nt = 0; nt < 8; ++nt) {
                u32 boff = (u32)(((kt * 16 + b2row) * LDB + nt * 8) * 2);
                u32 b_h[2], b_l[2];
                ldsm2t(bVh + boff, b_h);
                ldsm2t(bVl + boff, b_l);
                mma16816(VB[nt], Rh[kt], b_h);
                mma16816(VB[nt], Rh[kt], b_l);
                mma16816(VB[nt], Rl[kt], b_h);
            }
        }
        long o0 = (long)bh * 262144 + (16 * w + g) * 4096 + j * 64;
        long o1 = o0 + 8 * 4096;
#pragma unroll
        for (int nt = 0; nt < 8; ++nt) {
            int d = nt * 8 + 2 * tq;
            stPair(g_vbarH + o0 + d, g_vbarL + o0 + d, VB[nt][0], VB[nt][1]);
            stPair(g_vbarH + o1 + d, g_vbarL + o1 + d, VB[nt][2], VB[nt][3]);
        }
    }
}

// ---------------------------------------------------------------------------
// cstep v8 (hand-rolled): per (bh,s):
//   SL = scale*Q kbar^T + ent (registers); L = softmax_j (registers)
//   non-final: L -> smem; w = col-sums; qbar = L^T Q / w  (ldsm4t A)
//   final:     out = L vbar  (register A reuse)
// grid 4096, 128 thr
// ---------------------------------------------------------------------------
__global__ void __launch_bounds__(128)
cstep_kernel(const float* __restrict__ Qg, float* __restrict__ out, int is_final) {
    int bid = blockIdx.x, bh = bid >> 6, s = bid & 63;
    extern __shared__ char sm[];
    __nv_bfloat16* Qh = (__nv_bfloat16*)(sm + OFF_AH);
    __nv_bfloat16* Ql = (__nv_bfloat16*)(sm + OFF_AL);
    __nv_bfloat16* Lh = (__nv_bfloat16*)(sm + OFF_BH);   // kbar -> L
    __nv_bfloat16* Ll = (__nv_bfloat16*)(sm + OFF_BL);
    __nv_bfloat16* Vh = (__nv_bfloat16*)(sm + BO_VH);
    __nv_bfloat16* Vl = (__nv_bfloat16*)(sm + BO_VL);
    float* sEnt = (float*)(sm + (is_final ? 55296 : 36864));
    float* sW = sEnt + 64;
    int tid = threadIdx.x, w = tid >> 5, lane = tid & 31;
    int g = lane >> 2, tq = lane & 3;

    int koff = bh * 262144 + s * 4096;
    copyTile(smem_u32(Lh), g_kbarH + koff, tid);
    copyTile(smem_u32(Ll), g_kbarL + koff, tid);
    if (is_final) {
        copyTile(smem_u32(Vh), g_vbarH + koff, tid);
        copyTile(smem_u32(Vl), g_vbarL + koff, tid);
    }
    cpa_commit();
    stageHL(Qh, Ql, Qg + bh * 262144 + s * 64, 4096, tid);
    if (tid < 64) sEnt[tid] = g_ent[((bh << 6) + s) * 64 + tid];
    cpa_waitg<0>();
    __syncthreads();

    u32 bQh = smem_u32(Qh), bQl = smem_u32(Ql);
    u32 bLh = smem_u32(Lh), bLl = smem_u32(Ll);

    int l15 = lane & 15;
    int arow = 16 * w + ((lane >> 3) & 1) * 8 + (lane & 7);
    int aext = (lane >> 4) * 8;
    int b1row = l15 & 7, b1ext = (l15 >> 3) * 8;
    int b2row = (l15 >> 3) * 8 + (l15 & 7);
    // trans-A lane mapping (for L^T): row = k-index, col = m-index
    int atrow = (lane >> 4) * 8 + (lane & 7);
    int atcol = 16 * w + ((lane >> 3) & 1) * 8;

    // ---------------- GEMM1: SL[i][j] = Q(i,d).kbar(j,d) ----------------
    float S[8][4];
#pragma unroll
    for (int nt = 0; nt < 8; ++nt)
#pragma unroll
        for (int c = 0; c < 4; ++c) S[nt][c] = 0.f;

#pragma unroll
    for (int kt = 0; kt < 4; ++kt) {
        int k0 = kt << 4;
        u32 ah[4], al[4], b_h[2], b_l[2];
        u32 aoff = (u32)((arow * LDB + k0 + aext) * 2);
        ldsm4(bQh + aoff, ah);
        ldsm4(bQl + aoff, al);
#pragma unroll
        for (int nt = 0; nt < 8; ++nt) {
            u32 boff = (u32)(((nt * 8 + b1row) * LDB + k0 + b1ext) * 2);
            ldsm2(bLh + boff, b_h);
            ldsm2(bLl + boff, b_l);
            mma16816(S[nt], ah, b_h);
            mma16816(S[nt], ah, b_l);
            mma16816(S[nt], al, b_h);
        }
    }

    // ---------------- softmax over j (registers, + ent) ----------------
    {
        float mx0 = -1e30f, mx1 = -1e30f;
#pragma unroll
        for (int nt = 0; nt < 8; ++nt) {
            int j0 = nt * 8 + 2 * tq;
            float e0c = sEnt[j0], e1c = sEnt[j0 + 1];
            S[nt][0] = S[nt][0] * SCALE + e0c;
            S[nt][1] = S[nt][1] * SCALE + e1c;
            S[nt][2] = S[nt][2] * SCALE + e0c;
            S[nt][3] = S[nt][3] * SCALE + e1c;
            mx0 = fmaxf(mx0, fmaxf(S[nt][0], S[nt][1]));
            mx1 = fmaxf(mx1, fmaxf(S[nt][2], S[nt][3]));
        }
        mx0 = fmaxf(mx0, __shfl_xor_sync(0xffffffffu, mx0, 1));
        mx0 = fmaxf(mx0, __shfl_xor_sync(0xffffffffu, mx0, 2));
        mx1 = fmaxf(mx1, __shfl_xor_sync(0xffffffffu, mx1, 1));
        mx1 = fmaxf(mx1, __shfl_xor_sync(0xffffffffu, mx1, 2));
        float s0 = 0.f, s1 = 0.f;
#pragma unroll
        for (int nt = 0; nt < 8; ++nt) {
            S[nt][0] = __expf(S[nt][0] - mx0);
            S[nt][1] = __expf(S[nt][1] - mx0);
            S[nt][2] = __expf(S[nt][2] - mx1);
            S[nt][3] = __expf(S[nt][3] - mx1);
            s0 += S[nt][0] + S[nt][1];
            s1 += S[nt][2] + S[nt][3];
        }
        s0 += __shfl_xor_sync(0xffffffffu, s0, 1);
        s0 += __shfl_xor_sync(0xffffffffu, s0, 2);
        s1 += __shfl_xor_sync(0xffffffffu, s1, 1);
        s1 += __shfl_xor_sync(0xffffffffu, s1, 2);
        float i0 = 1.0f / s0, i1 = 1.0f / s1;
#pragma unroll
        for (int nt = 0; nt < 8; ++nt) {
            S[nt][0] *= i0; S[nt][1] *= i0;
            S[nt][2] *= i1; S[nt][3] *= i1;
        }
    }

    // L fragments (hi/lo) in registers
    u32 Rh[4][4], Rl[4][4];
#pragma unroll
    for (int kt = 0; kt < 4; ++kt) {
        const float* e = S[2 * kt];
        const float* o = S[2 * kt + 1];
        float h;
        Rh[kt][0] = pack2(e[0], e[1]);
        Rh[kt][1] = pack2(e[2], e[3]);
        Rh[kt][2] = pack2(o[0], o[1]);
        Rh[kt][3] = pack2(o[2], o[3]);
        float r0, r1, r2, r3;
        h = __bfloat162float(__float2bfloat16(e[0])); r0 = e[0] - h;
        h = __bfloat162float(__float2bfloat16(e[1])); r1 = e[1] - h;
        h = __bfloat162float(__float2bfloat16(e[2])); r2 = e[2] - h;
        h = __bfloat162float(__float2bfloat16(e[3])); r3 = e[3] - h;
        Rl[kt][0] = pack2(r0, r1);
        Rl[kt][1] = pack2(r2, r3);
        h = __bfloat162float(__float2bfloat16(o[0])); r0 = o[0] - h;
        h = __bfloat162float(__float2bfloat16(o[1])); r1 = o[1] - h;
        h = __bfloat162float(__float2bfloat16(o[2])); r2 = o[2] - h;
        h = __bfloat162float(__float2bfloat16(o[3])); r3 = o[3] - h;
        Rl[kt][2] = pack2(r0, r1);
        Rl[kt][3] = pack2(r2, r3);
    }

    if (is_final) {
        // out(i,d) = sum_j L(i,j) vbar(j,d): register A reuse, B=ldsm2t(V)
        u32 bVh = smem_u32(Vh), bVl = smem_u32(Vl);
        float OB[8][4];
#pragma unroll
        for (int nt = 0; nt < 8; ++nt)
#pragma unroll
            for (int c = 0; c < 4; ++c) OB[nt][c] = 0.f;
#pragma unroll
        for (int kt = 0; kt < 4; ++kt) {
#pragma unroll
            for (int nt = 0; nt < 8; ++nt) {
                u32 boff = (u32)(((kt * 16 + b2row) * LDB + nt * 8) * 2);
                u32 b_h[2], b_l[2];
                ldsm2t(bVh + boff, b_h);
                ldsm2t(bVl + boff, b_l);
                mma16816(OB[nt], Rh[kt], b_h);
                mma16816(OB[nt], Rh[kt], b_l);
                mma16816(OB[nt], Rl[kt], b_h);
            }
        }
        long o0 = (long)bh * 262144 + (16 * w + g) * 4096 + s * 64;
        long o1 = o0 + 8 * 4096;
#pragma unroll
        for (int nt = 0; nt < 8; ++nt) {
            int d = nt * 8 + 2 * tq;
            *reinterpret_cast<float2*>(out + o0 + d) =
                make_float2(OB[nt][0], OB[nt][1]);
            *reinterpret_cast<float2*>(out + o1 + d) =
                make_float2(OB[nt][2], OB[nt][3]);
        }
    } else {
        // store L hi/lo to smem (overwrite kbar tiles)
        int rA = 16 * w + g, rB = rA + 8;
#pragma unroll
        for (int kt = 0; kt < 4; ++kt) {
            int j0 = (2 * kt) * 8 + 2 * tq;
            int j1 = j0 + 8;
            *reinterpret_cast<u32*>(Lh + rA * LDB + j0) = Rh[kt][0];
            *reinterpret_cast<u32*>(Lh + rA * LDB + j1) = Rh[kt][2];
            *reinterpret_cast<u32*>(Lh + rB * LDB + j0) = Rh[kt][1];
            *reinterpret_cast<u32*>(Lh + rB * LDB + j1) = Rh[kt][3];
            *reinterpret_cast<u32*>(Ll + rA * LDB + j0) = Rl[kt][0];
            *reinterpret_cast<u32*>(Ll + rA * LDB + j1) = Rl[kt][2];
            *reinterpret_cast<u32*>(Ll + rB * LDB + j0) = Rl[kt][1];
            *reinterpret_cast<u32*>(Ll + rB * LDB + j1) = Rl[kt][3];
        }
        __syncthreads();
        if (tid < 64) {   // w_j = sum_i L[i][j] (hi+lo)
            float wv = 0.f;
#pragma unroll 8
            for (int i = 0; i < 64; ++i)
                wv += __bfloat162float(Lh[i * LDB + tid]) +
                      __bfloat162float(Ll[i * LDB + tid]);
            sW[tid] = 1.0f / wv;
        }
        // GEMM2: qbar_num(j,d) = sum_i L(i,j) Q(i,d); A = L^T via ldsm4t
        float QB[8][4];
#pragma unroll
        for (int nt = 0; nt < 8; ++nt)
#pragma unroll
            for (int c = 0; c < 4; ++c) QB[nt][c] = 0.f;
#pragma unroll
        for (int kt = 0; kt < 4; ++kt) {
            int k0 = kt << 4;
            u32 ah[4], al[4];
            u32 aoff = (u32)(((k0 + atrow) * LDB + atcol) * 2);
            ldsm4t(bLh + aoff, ah);
            ldsm4t(bLl + aoff, al);
#pragma unroll
            for (int nt = 0; nt < 8; ++nt) {
                u32 boff = (u32)(((k0 + b2row) * LDB + nt * 8) * 2);
                u32 b_h[2], b_l[2];
                ldsm2t(bQh + boff, b_h);
                ldsm2t(bQl + boff, b_l);
                mma16816(QB[nt], ah, b_h);
                mma16816(QB[nt], ah, b_l);
                mma16816(QB[nt], al, b_h);
            }
        }
        __syncthreads();   // sW visible
        int j0r = 16 * w + g, j1r = j0r + 8;
        float iw0 = sW[j0r], iw1 = sW[j1r];
        long o0 = (long)bh * 262144 + j0r * 4096 + s * 64;
        long o1 = (long)bh * 262144 + j1r * 4096 + s * 64;
#pragma unroll
        for (int nt = 0; nt < 8; ++nt) {
            int d = nt * 8 + 2 * tq;
            stPair(g_qbarH + o0 + d, g_qbarL + o0 + d,
                   QB[nt][0] * iw0, QB[nt][1] * iw0);
            stPair(g_qbarH + o1 + d, g_qbarL + o1 + d,
                   QB[nt][2] * iw1, QB[nt][3] * iw1);
        }
    }
}

// ---------------------------------------------------------------------------
extern "C" void kernel_launch(void* const* d_in, const int* in_sizes, int n_in,
                              void* d_out, int out_size) {
    const float* Q = (const float*)d_in[0];
    const float* K = (const float*)d_in[1];
    const float* V = (const float*)d_in[2];
    float* out = (float*)d_out;

    cudaFuncSetAttribute(bstep_kernel, cudaFuncAttributeMaxDynamicSharedMemorySize, SMEM_B_BIG);
    cudaFuncSetAttribute(cstep_kernel, cudaFuncAttributeMaxDynamicSharedMemorySize, SMEM_C_BIG);

    // step 0 (uniform L -> qbar == per-s mean of Q)
    qmean_kernel<<<1024, 256>>>(Q);
    bstep_kernel<<<4096, 128, SMEM_B_SMALL>>>(K, V, 1, 0);
    cstep_kernel<<<4096, 128, SMEM_C_SMALL>>>(Q, out, 0);
    // step 1
    bstep_kernel<<<4096, 128, SMEM_B_SMALL>>>(K, V, 0, 0);
    cstep_kernel<<<4096, 128, SMEM_C_SMALL>>>(Q, out, 0);
    // step 2
    bstep_kernel<<<4096, 128, SMEM_B_BIG>>>(K, V, 0, 1);   // + vbar
    cstep_kernel<<<4096, 128, SMEM_C_BIG>>>(Q, out, 1);    // final: out = L vbar
}